// round 4
// baseline (speedup 1.0000x reference)
#include <cuda_runtime.h>
#include <cuda_bf16.h>
#include <math.h>
#include <stdint.h>

#define NROWS 32768
#define DDIM  256
#define EPSV  1e-5f
#define KC    64
#define STAGE_BYTES 98304        // Ahi 16K | Alo 16K | Bhi 32K | Blo 32K
#define SMEM_DYN (2 * STAGE_BYTES + 1024)

// ---------------- device scratch (no allocations allowed) ----------------
__device__ __nv_bfloat16 g_Xhi[NROWS * DDIM];
__device__ __nv_bfloat16 g_Xlo[NROWS * DDIM];
__device__ __nv_bfloat16 g_Yhi[NROWS * DDIM];
__device__ __nv_bfloat16 g_Ylo[NROWS * DDIM];
__device__ __nv_bfloat16 g_Bhi[4][DDIM * DDIM];   // B[n][k] = s_k * W[k][n], hi
__device__ __nv_bfloat16 g_Blo[4][DDIM * DDIM];
__device__ float g_bias [4][DDIM];                 // b'[n] = b[n] + sum_k t_k W[k][n]
__device__ float g_sum  [3 * DDIM];
__device__ float g_sumsq[3 * DDIM];
__device__ float g_scale[3 * DDIM];
__device__ float g_shift[3 * DDIM];

// ---------------- helpers ----------------
__device__ __forceinline__ uint32_t sm_u32(const void* p) {
    return (uint32_t)__cvta_generic_to_shared(p);
}
__device__ __forceinline__ float gelu_exact(float x) {
    return 0.5f * x * (1.0f + erff(x * 0.70710678118654752440f));
}
__device__ __forceinline__ void split2(float v, __nv_bfloat16& h, __nv_bfloat16& l) {
    h = __float2bfloat16(v);
    l = __float2bfloat16(v - __bfloat162float(h));
}
__device__ __forceinline__ uint32_t pack2(__nv_bfloat16 a, __nv_bfloat16 b) {
    __nv_bfloat162 t = __halves2bfloat162(a, b);
    return *reinterpret_cast<uint32_t*>(&t);
}
__device__ __forceinline__ uint32_t swz(uint32_t off) {
    return off ^ ((off >> 3) & 0x70);
}

#define CP16(sm, gp) \
    asm volatile("cp.async.cg.shared.global [%0], [%1], 16;" :: "r"(sm), "l"(gp) : "memory")
#define CP_COMMIT() asm volatile("cp.async.commit_group;" ::: "memory")
#define CP_WAIT1()  asm volatile("cp.async.wait_group 1;" ::: "memory")
#define CP_WAIT0()  asm volatile("cp.async.wait_group 0;" ::: "memory")

#define LDSM_X4(r, addr) \
    asm volatile("ldmatrix.sync.aligned.m8n8.x4.shared.b16 {%0,%1,%2,%3}, [%4];" \
        : "=r"((r)[0]), "=r"((r)[1]), "=r"((r)[2]), "=r"((r)[3]) : "r"(addr))
#define LDSM_X2(r0, r1, addr) \
    asm volatile("ldmatrix.sync.aligned.m8n8.x2.shared.b16 {%0,%1}, [%2];" \
        : "=r"(r0), "=r"(r1) : "r"(addr))

__device__ __forceinline__ void mma16816(float* c, const uint32_t* a, uint32_t b0, uint32_t b1) {
    asm volatile(
        "mma.sync.aligned.m16n8k16.row.col.f32.bf16.bf16.f32 "
        "{%0,%1,%2,%3}, {%4,%5,%6,%7}, {%8,%9}, {%0,%1,%2,%3};"
        : "+f"(c[0]), "+f"(c[1]), "+f"(c[2]), "+f"(c[3])
        : "r"(a[0]), "r"(a[1]), "r"(a[2]), "r"(a[3]), "r"(b0), "r"(b1));
}

// ---------------- small kernels ----------------
__global__ void zero_stats_kernel() {
    int i = threadIdx.x;
    if (i < 3 * DDIM) { g_sum[i] = 0.f; g_sumsq[i] = 0.f; }
}

__global__ void finalize_stats_kernel(int layer, const float* __restrict__ g,
                                      const float* __restrict__ be) {
    int c = threadIdx.x;
    const float inv = 1.0f / (float)NROWS;
    float mu  = g_sum  [layer * DDIM + c] * inv;
    float var = g_sumsq[layer * DDIM + c] * inv - mu * mu;
    float s = rsqrtf(var + EPSV) * g[c];
    g_scale[layer * DDIM + c] = s;
    g_shift[layer * DDIM + c] = be[c] - mu * s;
}

__global__ void gather_split_kernel(const int* __restrict__ ids,
                                    const float* __restrict__ table) {
    int idx = blockIdx.x * blockDim.x + threadIdx.x;   // float4 index
    int row = idx >> 6;
    int q   = idx & 63;
    int src = ids[row];
    float4 v = reinterpret_cast<const float4*>(table + (size_t)src * DDIM)[q];
    __nv_bfloat16 h0, h1, h2, h3, l0, l1, l2, l3;
    split2(v.x, h0, l0); split2(v.y, h1, l1); split2(v.z, h2, l2); split2(v.w, h3, l3);
    reinterpret_cast<uint2*>(g_Xhi)[idx] = make_uint2(pack2(h0, h1), pack2(h2, h3));
    reinterpret_cast<uint2*>(g_Xlo)[idx] = make_uint2(pack2(l0, l1), pack2(l2, l3));
}

__global__ void prep_w_kernel(const float* __restrict__ W, const float* __restrict__ b,
                              int layer, int use_bn) {
    __shared__ float red[DDIM];
    int n = blockIdx.x, k = threadIdx.x;
    float w = W[k * DDIM + n];
    float s = 1.f, t = 0.f;
    if (use_bn) {
        s = g_scale[(layer - 1) * DDIM + k];
        t = g_shift[(layer - 1) * DDIM + k];
    }
    __nv_bfloat16 h, l;
    split2(w * s, h, l);
    g_Bhi[layer][n * DDIM + k] = h;
    g_Blo[layer][n * DDIM + k] = l;
    red[k] = t * w;
    __syncthreads();
    for (int st = 128; st > 0; st >>= 1) {
        if (k < st) red[k] += red[k + st];
        __syncthreads();
    }
    if (k == 0) g_bias[layer][n] = b[n] + red[0];
}

// ---------------- main fused GEMM layer (HMMA mma.sync, split-bf16 x3) ----------------
// CTA: M=128 x N=256, 16 warps (4M x 4N), warp tile 32x64. K chunks of 64, cp.async 2-stage.
template<int STATS, int FINAL>
__global__ __launch_bounds__(512, 1)
void gemm_kernel(const __nv_bfloat16* __restrict__ Ahi,
                 const __nv_bfloat16* __restrict__ Alo,
                 const __nv_bfloat16* __restrict__ Bhi,
                 const __nv_bfloat16* __restrict__ Blo,
                 const float* __restrict__ bias,
                 int layer,
                 float* __restrict__ outF,
                 __nv_bfloat16* __restrict__ outHi,
                 __nv_bfloat16* __restrict__ outLo)
{
    extern __shared__ char dyn_smem[];
    const int tid  = threadIdx.x;
    const int lane = tid & 31;
    const int wid  = tid >> 5;
    const int m_warp = (wid >> 2) * 32;
    const int n_warp = (wid & 3) * 64;
    const int r0 = blockIdx.x * 128;

    const uint32_t dyn0 = sm_u32(dyn_smem);
    const uint32_t su   = (dyn0 + 1023) & ~1023u;   // 1KB-aligned SMEM base

    float acc[2][8][4];
    #pragma unroll
    for (int i = 0; i < 2; i++)
        #pragma unroll
        for (int j = 0; j < 8; j++)
            #pragma unroll
            for (int q = 0; q < 4; q++) acc[i][j][q] = 0.f;

    // --- cp.async issue of one K-chunk into stage s ---
    auto issue = [&](int c) {
        const uint32_t sb = su + (c & 1) * STAGE_BYTES;
        const int kt = c * KC;
        #pragma unroll
        for (int i = 0; i < 2; i++) {           // A: 128 rows x 8 x 16B (hi+lo)
            int idx = tid + i * 512;
            int row = idx >> 3, q = idx & 7;
            uint32_t sw = swz((uint32_t)(row * 128 + q * 16));
            const size_t g = (size_t)(r0 + row) * DDIM + kt + q * 8;
            CP16(sb + sw,         Ahi + g);
            CP16(sb + 16384 + sw, Alo + g);
        }
        #pragma unroll
        for (int i = 0; i < 4; i++) {           // B: 256 rows x 8 x 16B (hi+lo)
            int idx = tid + i * 512;
            int row = idx >> 3, q = idx & 7;
            uint32_t sw = swz((uint32_t)(row * 128 + q * 16));
            const size_t g = (size_t)row * DDIM + kt + q * 8;
            CP16(sb + 32768 + sw, Bhi + g);
            CP16(sb + 65536 + sw, Blo + g);
        }
        CP_COMMIT();
    };

    issue(0);
    for (int c = 0; c < 4; c++) {
        __syncthreads();                 // nobody still reading the buffer we refill
        if (c < 3) { issue(c + 1); CP_WAIT1(); } else { CP_WAIT0(); }
        __syncthreads();                 // chunk c visible to all

        const uint32_t sa = su + (c & 1) * STAGE_BYTES;
        #pragma unroll
        for (int ks = 0; ks < 4; ks++) {
            uint32_t a_hi[2][4], a_lo[2][4];
            #pragma unroll
            for (int i = 0; i < 2; i++) {
                uint32_t off = (uint32_t)((m_warp + i * 16 + (lane & 15)) * 128
                                          + ks * 32 + (lane >> 4) * 16);
                uint32_t ad = sa + swz(off);
                LDSM_X4(a_hi[i], ad);
                LDSM_X4(a_lo[i], ad + 16384);
            }
            #pragma unroll
            for (int j = 0; j < 8; j++) {
                uint32_t offb = (uint32_t)((n_warp + j * 8 + (lane & 7)) * 128
                                           + ks * 32 + ((lane >> 3) & 1) * 16);
                uint32_t adb = sa + 32768 + swz(offb);
                uint32_t bh0, bh1, bl0, bl1;
                LDSM_X2(bh0, bh1, adb);
                LDSM_X2(bl0, bl1, adb + 32768);
                #pragma unroll
                for (int i = 0; i < 2; i++) {
                    mma16816(acc[i][j], a_hi[i], bh0, bh1);
                    mma16816(acc[i][j], a_hi[i], bl0, bl1);
                    mma16816(acc[i][j], a_lo[i], bh0, bh1);
                }
            }
        }
    }

    // ---- epilogue: bias + exact GELU + stores + column stats ----
    #pragma unroll
    for (int j = 0; j < 8; j++) {
        const int col0 = n_warp + j * 8 + (lane & 3) * 2;
        const float bi0 = bias[col0], bi1 = bias[col0 + 1];
        float su0 = 0.f, su1 = 0.f, sq0 = 0.f, sq1 = 0.f;
        #pragma unroll
        for (int i = 0; i < 2; i++) {
            const int rowA = r0 + m_warp + i * 16 + (lane >> 2);
            float v0 = gelu_exact(acc[i][j][0] + bi0);
            float v1 = gelu_exact(acc[i][j][1] + bi1);
            float v2 = gelu_exact(acc[i][j][2] + bi0);
            float v3 = gelu_exact(acc[i][j][3] + bi1);
            if (STATS) {
                su0 += v0 + v2; su1 += v1 + v3;
                sq0 += v0 * v0 + v2 * v2; sq1 += v1 * v1 + v3 * v3;
            }
            if (FINAL) {
                *reinterpret_cast<float2*>(outF + (size_t)rowA * DDIM + col0)
                    = make_float2(v0, v1);
                *reinterpret_cast<float2*>(outF + (size_t)(rowA + 8) * DDIM + col0)
                    = make_float2(v2, v3);
            } else {
                __nv_bfloat16 h0, l0, h1, l1;
                split2(v0, h0, l0); split2(v1, h1, l1);
                *reinterpret_cast<uint32_t*>(outHi + (size_t)rowA * DDIM + col0) = pack2(h0, h1);
                *reinterpret_cast<uint32_t*>(outLo + (size_t)rowA * DDIM + col0) = pack2(l0, l1);
                split2(v2, h0, l0); split2(v3, h1, l1);
                *reinterpret_cast<uint32_t*>(outHi + (size_t)(rowA + 8) * DDIM + col0) = pack2(h0, h1);
                *reinterpret_cast<uint32_t*>(outLo + (size_t)(rowA + 8) * DDIM + col0) = pack2(l0, l1);
            }
        }
        if (STATS) {
            #pragma unroll
            for (int m = 4; m <= 16; m <<= 1) {
                su0 += __shfl_xor_sync(0xFFFFFFFFu, su0, m);
                su1 += __shfl_xor_sync(0xFFFFFFFFu, su1, m);
                sq0 += __shfl_xor_sync(0xFFFFFFFFu, sq0, m);
                sq1 += __shfl_xor_sync(0xFFFFFFFFu, sq1, m);
            }
            if ((lane >> 2) == 0) {
                atomicAdd(&g_sum  [layer * DDIM + col0],     su0);
                atomicAdd(&g_sum  [layer * DDIM + col0 + 1], su1);
                atomicAdd(&g_sumsq[layer * DDIM + col0],     sq0);
                atomicAdd(&g_sumsq[layer * DDIM + col0 + 1], sq1);
            }
        }
    }
}

// ---------------- launch ----------------
extern "C" void kernel_launch(void* const* d_in, const int* in_sizes, int n_in,
                              void* d_out, int out_size) {
    const int*   ids   = (const int*)  d_in[0];
    const float* table = (const float*)d_in[1];
    const float* W[4]  = {(const float*)d_in[2], (const float*)d_in[4],
                          (const float*)d_in[6], (const float*)d_in[8]};
    const float* b[4]  = {(const float*)d_in[3], (const float*)d_in[5],
                          (const float*)d_in[7], (const float*)d_in[9]};
    const float* g[3]  = {(const float*)d_in[10], (const float*)d_in[12], (const float*)d_in[14]};
    const float* be[3] = {(const float*)d_in[11], (const float*)d_in[13], (const float*)d_in[15]};
    float* out = (float*)d_out;

    cudaFuncSetAttribute(gemm_kernel<1, 0>, cudaFuncAttributeMaxDynamicSharedMemorySize, SMEM_DYN);
    cudaFuncSetAttribute(gemm_kernel<0, 1>, cudaFuncAttributeMaxDynamicSharedMemorySize, SMEM_DYN);

    __nv_bfloat16 *Xhi, *Xlo, *Yhi, *Ylo, *Bh, *Bl;
    float *bs;
    cudaGetSymbolAddress((void**)&Xhi, g_Xhi);
    cudaGetSymbolAddress((void**)&Xlo, g_Xlo);
    cudaGetSymbolAddress((void**)&Yhi, g_Yhi);
    cudaGetSymbolAddress((void**)&Ylo, g_Ylo);
    cudaGetSymbolAddress((void**)&Bh,  g_Bhi);
    cudaGetSymbolAddress((void**)&Bl,  g_Blo);
    cudaGetSymbolAddress((void**)&bs,  g_bias);

    const dim3 grid(NROWS / 128), blk(512);

    zero_stats_kernel<<<1, 768>>>();
    gather_split_kernel<<<NROWS * DDIM / 4 / 256, 256>>>(ids, table);
    prep_w_kernel<<<DDIM, DDIM>>>(W[0], b[0], 0, 0);

    gemm_kernel<1, 0><<<grid, blk, SMEM_DYN>>>(
        Xhi, Xlo, Bh + 0 * DDIM * DDIM, Bl + 0 * DDIM * DDIM, bs + 0 * DDIM,
        0, nullptr, Yhi, Ylo);
    finalize_stats_kernel<<<1, DDIM>>>(0, g[0], be[0]);
    prep_w_kernel<<<DDIM, DDIM>>>(W[1], b[1], 1, 1);

    gemm_kernel<1, 0><<<grid, blk, SMEM_DYN>>>(
        Yhi, Ylo, Bh + 1 * DDIM * DDIM, Bl + 1 * DDIM * DDIM, bs + 1 * DDIM,
        1, nullptr, Xhi, Xlo);
    finalize_stats_kernel<<<1, DDIM>>>(1, g[1], be[1]);
    prep_w_kernel<<<DDIM, DDIM>>>(W[2], b[2], 2, 1);

    gemm_kernel<1, 0><<<grid, blk, SMEM_DYN>>>(
        Xhi, Xlo, Bh + 2 * DDIM * DDIM, Bl + 2 * DDIM * DDIM, bs + 2 * DDIM,
        2, nullptr, Yhi, Ylo);
    finalize_stats_kernel<<<1, DDIM>>>(2, g[2], be[2]);
    prep_w_kernel<<<DDIM, DDIM>>>(W[3], b[3], 3, 1);

    gemm_kernel<0, 1><<<grid, blk, SMEM_DYN>>>(
        Yhi, Ylo, Bh + 3 * DDIM * DDIM, Bl + 3 * DDIM * DDIM, bs + 3 * DDIM,
        3, out, nullptr, nullptr);
}

// round 5
// speedup vs baseline: 1.0081x; 1.0081x over previous
#include <cuda_runtime.h>
#include <cuda_bf16.h>
#include <math.h>
#include <stdint.h>

#define NROWS 32768
#define DDIM  256
#define EPSV  1e-5f
#define KC    32
#define NCHUNK 8
#define STAGES 4
// Stage: Ahi 8K | Alo 8K | Bhi 16K | Blo 16K = 48K
#define STAGE_BYTES 49152
#define SMEM_DYN (STAGES * STAGE_BYTES + 1024)

// ---------------- device scratch (no allocations allowed) ----------------
__device__ __nv_bfloat16 g_Xhi[NROWS * DDIM];
__device__ __nv_bfloat16 g_Xlo[NROWS * DDIM];
__device__ __nv_bfloat16 g_Yhi[NROWS * DDIM];
__device__ __nv_bfloat16 g_Ylo[NROWS * DDIM];
__device__ __nv_bfloat16 g_Bhi[4][DDIM * DDIM];   // B[n][k] = s_k * W[k][n], hi
__device__ __nv_bfloat16 g_Blo[4][DDIM * DDIM];
__device__ float g_bias [4][DDIM];                 // b'[n] = b[n] + sum_k t_k W[k][n]
__device__ float g_sum  [3 * DDIM];
__device__ float g_sumsq[3 * DDIM];
__device__ float g_scale[3 * DDIM];
__device__ float g_shift[3 * DDIM];

// ---------------- helpers ----------------
__device__ __forceinline__ uint32_t sm_u32(const void* p) {
    return (uint32_t)__cvta_generic_to_shared(p);
}
__device__ __forceinline__ float gelu_exact(float x) {
    return 0.5f * x * (1.0f + erff(x * 0.70710678118654752440f));
}
__device__ __forceinline__ void split2(float v, __nv_bfloat16& h, __nv_bfloat16& l) {
    h = __float2bfloat16(v);
    l = __float2bfloat16(v - __bfloat162float(h));
}
__device__ __forceinline__ uint32_t pack2(__nv_bfloat16 a, __nv_bfloat16 b) {
    __nv_bfloat162 t = __halves2bfloat162(a, b);
    return *reinterpret_cast<uint32_t*>(&t);
}
// SW64 swizzle for 64-byte rows (8-row x 64B atom)
__device__ __forceinline__ uint32_t swz64(uint32_t off) {
    return off ^ ((off >> 3) & 0x30);
}

#define CP16(sm, gp) \
    asm volatile("cp.async.cg.shared.global [%0], [%1], 16;" :: "r"(sm), "l"(gp) : "memory")
#define CP_COMMIT() asm volatile("cp.async.commit_group;" ::: "memory")
#define CP_WAITN(n) asm volatile("cp.async.wait_group %0;" :: "n"(n) : "memory")

#define LDSM_X4(r, addr) \
    asm volatile("ldmatrix.sync.aligned.m8n8.x4.shared.b16 {%0,%1,%2,%3}, [%4];" \
        : "=r"((r)[0]), "=r"((r)[1]), "=r"((r)[2]), "=r"((r)[3]) : "r"(addr))

__device__ __forceinline__ void mma16816(float* c, const uint32_t* a, uint32_t b0, uint32_t b1) {
    asm volatile(
        "mma.sync.aligned.m16n8k16.row.col.f32.bf16.bf16.f32 "
        "{%0,%1,%2,%3}, {%4,%5,%6,%7}, {%8,%9}, {%0,%1,%2,%3};"
        : "+f"(c[0]), "+f"(c[1]), "+f"(c[2]), "+f"(c[3])
        : "r"(a[0]), "r"(a[1]), "r"(a[2]), "r"(a[3]), "r"(b0), "r"(b1));
}

// ---------------- small kernels ----------------
__global__ void zero_stats_kernel() {
    int i = threadIdx.x;
    if (i < 3 * DDIM) { g_sum[i] = 0.f; g_sumsq[i] = 0.f; }
}

__global__ void finalize_stats_kernel(int layer, const float* __restrict__ g,
                                      const float* __restrict__ be) {
    int c = threadIdx.x;
    const float inv = 1.0f / (float)NROWS;
    float mu  = g_sum  [layer * DDIM + c] * inv;
    float var = g_sumsq[layer * DDIM + c] * inv - mu * mu;
    float s = rsqrtf(var + EPSV) * g[c];
    g_scale[layer * DDIM + c] = s;
    g_shift[layer * DDIM + c] = be[c] - mu * s;
}

__global__ void gather_split_kernel(const int* __restrict__ ids,
                                    const float* __restrict__ table) {
    int idx = blockIdx.x * blockDim.x + threadIdx.x;   // float4 index
    int row = idx >> 6;
    int q   = idx & 63;
    int src = ids[row];
    float4 v = reinterpret_cast<const float4*>(table + (size_t)src * DDIM)[q];
    __nv_bfloat16 h0, h1, h2, h3, l0, l1, l2, l3;
    split2(v.x, h0, l0); split2(v.y, h1, l1); split2(v.z, h2, l2); split2(v.w, h3, l3);
    reinterpret_cast<uint2*>(g_Xhi)[idx] = make_uint2(pack2(h0, h1), pack2(h2, h3));
    reinterpret_cast<uint2*>(g_Xlo)[idx] = make_uint2(pack2(l0, l1), pack2(l2, l3));
}

__global__ void prep_w_kernel(const float* __restrict__ W, const float* __restrict__ b,
                              int layer, int use_bn) {
    __shared__ float red[DDIM];
    int n = blockIdx.x, k = threadIdx.x;
    float w = W[k * DDIM + n];
    float s = 1.f, t = 0.f;
    if (use_bn) {
        s = g_scale[(layer - 1) * DDIM + k];
        t = g_shift[(layer - 1) * DDIM + k];
    }
    __nv_bfloat16 h, l;
    split2(w * s, h, l);
    g_Bhi[layer][n * DDIM + k] = h;
    g_Blo[layer][n * DDIM + k] = l;
    red[k] = t * w;
    __syncthreads();
    for (int st = 128; st > 0; st >>= 1) {
        if (k < st) red[k] += red[k + st];
        __syncthreads();
    }
    if (k == 0) g_bias[layer][n] = b[n] + red[0];
}

// ---------------- main fused GEMM layer (HMMA mma.sync, split-bf16 x3) ----------------
// CTA: M=128 x N=256, 16 warps (4M x 4N), warp tile 32x64.
// K chunks of 32, 4-stage cp.async pipeline, one barrier per chunk.
template<int STATS, int FINAL>
__global__ __launch_bounds__(512, 1)
void gemm_kernel(const __nv_bfloat16* __restrict__ Ahi,
                 const __nv_bfloat16* __restrict__ Alo,
                 const __nv_bfloat16* __restrict__ Bhi,
                 const __nv_bfloat16* __restrict__ Blo,
                 const float* __restrict__ bias,
                 int layer,
                 float* __restrict__ outF,
                 __nv_bfloat16* __restrict__ outHi,
                 __nv_bfloat16* __restrict__ outLo)
{
    extern __shared__ char dyn_smem[];
    const int tid  = threadIdx.x;
    const int lane = tid & 31;
    const int wid  = tid >> 5;
    const int m_warp = (wid >> 2) * 32;
    const int n_warp = (wid & 3) * 64;
    const int r0 = blockIdx.x * 128;

    const uint32_t dyn0 = sm_u32(dyn_smem);
    const uint32_t su   = (dyn0 + 1023) & ~1023u;   // 1KB-aligned SMEM base

    float acc[2][8][4];
    #pragma unroll
    for (int i = 0; i < 2; i++)
        #pragma unroll
        for (int j = 0; j < 8; j++)
            #pragma unroll
            for (int q = 0; q < 4; q++) acc[i][j][q] = 0.f;

    // --- cp.async issue of one K-chunk (KC=32, 64B rows) into stage c%4 ---
    auto issue = [&](int c) {
        const uint32_t sb = su + (c & 3) * STAGE_BYTES;
        const int kt = c * KC;
        {   // A: 128 rows x 4 x 16B (hi+lo), 512 chunks per half, 1/thread
            int row = tid >> 2, q = tid & 3;
            uint32_t sw = swz64((uint32_t)(row * 64 + q * 16));
            const size_t g = (size_t)(r0 + row) * DDIM + kt + q * 8;
            CP16(sb + sw,        Ahi + g);
            CP16(sb + 8192 + sw, Alo + g);
        }
        #pragma unroll
        for (int i = 0; i < 2; i++) {   // B: 256 rows x 4 x 16B (hi+lo), 1024 per half
            int idx = tid + i * 512;
            int row = idx >> 2, q = idx & 3;
            uint32_t sw = swz64((uint32_t)(row * 64 + q * 16));
            const size_t g = (size_t)row * DDIM + kt + q * 8;
            CP16(sb + 16384 + sw, Bhi + g);
            CP16(sb + 32768 + sw, Blo + g);
        }
        CP_COMMIT();
    };

    // prologue: fill 3 stages
    issue(0); issue(1); issue(2);

    // A-frag lane addressing (row-major A, 16x16 frag = 4 m8n8)
    const uint32_t a_row = (uint32_t)(lane & 15);
    const uint32_t a_kh  = (uint32_t)(lane >> 4);
    // B-frag lane addressing (paired j/j+1 in one x4)
    const uint32_t b_row = (uint32_t)(((lane >> 4) & 1) * 8 + (lane & 7));
    const uint32_t b_kh  = (uint32_t)((lane >> 3) & 1);

    #pragma unroll
    for (int c = 0; c < NCHUNK; c++) {
        // wait for stage c data: pending newest allowed = issued_before - (c+1)
        if      (c <  NCHUNK - 2) CP_WAITN(2);
        else if (c == NCHUNK - 2) CP_WAITN(1);
        else                      CP_WAITN(0);
        __syncthreads();
        if (c + 3 < NCHUNK) issue(c + 3);

        const uint32_t sa = su + (c & 3) * STAGE_BYTES;
        #pragma unroll
        for (int ks = 0; ks < 2; ks++) {
            uint32_t a_hi[2][4], a_lo[2][4];
            #pragma unroll
            for (int i = 0; i < 2; i++) {
                uint32_t off = (m_warp + i * 16 + a_row) * 64 + ks * 32 + a_kh * 16;
                uint32_t ad = sa + swz64(off);
                LDSM_X4(a_hi[i], ad);
                LDSM_X4(a_lo[i], ad + 8192);
            }
            #pragma unroll
            for (int jp = 0; jp < 4; jp++) {
                uint32_t off = (n_warp + jp * 16 + b_row) * 64 + ks * 32 + b_kh * 16;
                uint32_t ad = sa + 16384 + swz64(off);
                uint32_t bh[4], bl[4];
                LDSM_X4(bh, ad);
                LDSM_X4(bl, ad + 16384);
                #pragma unroll
                for (int i = 0; i < 2; i++) {
                    mma16816(acc[i][2 * jp],     a_hi[i], bh[0], bh[1]);
                    mma16816(acc[i][2 * jp],     a_hi[i], bl[0], bl[1]);
                    mma16816(acc[i][2 * jp],     a_lo[i], bh[0], bh[1]);
                    mma16816(acc[i][2 * jp + 1], a_hi[i], bh[2], bh[3]);
                    mma16816(acc[i][2 * jp + 1], a_hi[i], bl[2], bl[3]);
                    mma16816(acc[i][2 * jp + 1], a_lo[i], bh[2], bh[3]);
                }
            }
        }
    }

    // ---- epilogue: bias + exact GELU + stores + column stats ----
    #pragma unroll
    for (int j = 0; j < 8; j++) {
        const int col0 = n_warp + j * 8 + (lane & 3) * 2;
        const float bi0 = bias[col0], bi1 = bias[col0 + 1];
        float su0 = 0.f, su1 = 0.f, sq0 = 0.f, sq1 = 0.f;
        #pragma unroll
        for (int i = 0; i < 2; i++) {
            const int rowA = r0 + m_warp + i * 16 + (lane >> 2);
            float v0 = gelu_exact(acc[i][j][0] + bi0);
            float v1 = gelu_exact(acc[i][j][1] + bi1);
            float v2 = gelu_exact(acc[i][j][2] + bi0);
            float v3 = gelu_exact(acc[i][j][3] + bi1);
            if (STATS) {
                su0 += v0 + v2; su1 += v1 + v3;
                sq0 += v0 * v0 + v2 * v2; sq1 += v1 * v1 + v3 * v3;
            }
            if (FINAL) {
                *reinterpret_cast<float2*>(outF + (size_t)rowA * DDIM + col0)
                    = make_float2(v0, v1);
                *reinterpret_cast<float2*>(outF + (size_t)(rowA + 8) * DDIM + col0)
                    = make_float2(v2, v3);
            } else {
                __nv_bfloat16 h0, l0, h1, l1;
                split2(v0, h0, l0); split2(v1, h1, l1);
                *reinterpret_cast<uint32_t*>(outHi + (size_t)rowA * DDIM + col0) = pack2(h0, h1);
                *reinterpret_cast<uint32_t*>(outLo + (size_t)rowA * DDIM + col0) = pack2(l0, l1);
                split2(v2, h0, l0); split2(v3, h1, l1);
                *reinterpret_cast<uint32_t*>(outHi + (size_t)(rowA + 8) * DDIM + col0) = pack2(h0, h1);
                *reinterpret_cast<uint32_t*>(outLo + (size_t)(rowA + 8) * DDIM + col0) = pack2(l0, l1);
            }
        }
        if (STATS) {
            #pragma unroll
            for (int m = 4; m <= 16; m <<= 1) {
                su0 += __shfl_xor_sync(0xFFFFFFFFu, su0, m);
                su1 += __shfl_xor_sync(0xFFFFFFFFu, su1, m);
                sq0 += __shfl_xor_sync(0xFFFFFFFFu, sq0, m);
                sq1 += __shfl_xor_sync(0xFFFFFFFFu, sq1, m);
            }
            if ((lane >> 2) == 0) {
                atomicAdd(&g_sum  [layer * DDIM + col0],     su0);
                atomicAdd(&g_sum  [layer * DDIM + col0 + 1], su1);
                atomicAdd(&g_sumsq[layer * DDIM + col0],     sq0);
                atomicAdd(&g_sumsq[layer * DDIM + col0 + 1], sq1);
            }
        }
    }
}

// ---------------- launch ----------------
extern "C" void kernel_launch(void* const* d_in, const int* in_sizes, int n_in,
                              void* d_out, int out_size) {
    const int*   ids   = (const int*)  d_in[0];
    const float* table = (const float*)d_in[1];
    const float* W[4]  = {(const float*)d_in[2], (const float*)d_in[4],
                          (const float*)d_in[6], (const float*)d_in[8]};
    const float* b[4]  = {(const float*)d_in[3], (const float*)d_in[5],
                          (const float*)d_in[7], (const float*)d_in[9]};
    const float* g[3]  = {(const float*)d_in[10], (const float*)d_in[12], (const float*)d_in[14]};
    const float* be[3] = {(const float*)d_in[11], (const float*)d_in[13], (const float*)d_in[15]};
    float* out = (float*)d_out;

    cudaFuncSetAttribute(gemm_kernel<1, 0>, cudaFuncAttributeMaxDynamicSharedMemorySize, SMEM_DYN);
    cudaFuncSetAttribute(gemm_kernel<0, 1>, cudaFuncAttributeMaxDynamicSharedMemorySize, SMEM_DYN);

    __nv_bfloat16 *Xhi, *Xlo, *Yhi, *Ylo, *Bh, *Bl;
    float *bs;
    cudaGetSymbolAddress((void**)&Xhi, g_Xhi);
    cudaGetSymbolAddress((void**)&Xlo, g_Xlo);
    cudaGetSymbolAddress((void**)&Yhi, g_Yhi);
    cudaGetSymbolAddress((void**)&Ylo, g_Ylo);
    cudaGetSymbolAddress((void**)&Bh,  g_Bhi);
    cudaGetSymbolAddress((void**)&Bl,  g_Blo);
    cudaGetSymbolAddress((void**)&bs,  g_bias);

    const dim3 grid(NROWS / 128), blk(512);

    zero_stats_kernel<<<1, 768>>>();
    gather_split_kernel<<<NROWS * DDIM / 4 / 256, 256>>>(ids, table);
    prep_w_kernel<<<DDIM, DDIM>>>(W[0], b[0], 0, 0);

    gemm_kernel<1, 0><<<grid, blk, SMEM_DYN>>>(
        Xhi, Xlo, Bh + 0 * DDIM * DDIM, Bl + 0 * DDIM * DDIM, bs + 0 * DDIM,
        0, nullptr, Yhi, Ylo);
    finalize_stats_kernel<<<1, DDIM>>>(0, g[0], be[0]);
    prep_w_kernel<<<DDIM, DDIM>>>(W[1], b[1], 1, 1);

    gemm_kernel<1, 0><<<grid, blk, SMEM_DYN>>>(
        Yhi, Ylo, Bh + 1 * DDIM * DDIM, Bl + 1 * DDIM * DDIM, bs + 1 * DDIM,
        1, nullptr, Xhi, Xlo);
    finalize_stats_kernel<<<1, DDIM>>>(1, g[1], be[1]);
    prep_w_kernel<<<DDIM, DDIM>>>(W[2], b[2], 2, 1);

    gemm_kernel<1, 0><<<grid, blk, SMEM_DYN>>>(
        Xhi, Xlo, Bh + 2 * DDIM * DDIM, Bl + 2 * DDIM * DDIM, bs + 2 * DDIM,
        2, nullptr, Yhi, Ylo);
    finalize_stats_kernel<<<1, DDIM>>>(2, g[2], be[2]);
    prep_w_kernel<<<DDIM, DDIM>>>(W[3], b[3], 3, 1);

    gemm_kernel<0, 1><<<grid, blk, SMEM_DYN>>>(
        Yhi, Ylo, Bh + 3 * DDIM * DDIM, Bl + 3 * DDIM * DDIM, bs + 3 * DDIM,
        3, out, nullptr, nullptr);
}

// round 6
// speedup vs baseline: 1.0142x; 1.0061x over previous
#include <cuda_runtime.h>
#include <cuda_bf16.h>
#include <math.h>
#include <stdint.h>

#define NROWS 32768
#define DDIM  256
#define EPSV  1e-5f
#define KC    32
#define NCHUNK 8
#define STAGES 4
// Stage: Ahi 8K | Alo 8K | Bhi 16K | Blo 16K = 48K
#define STAGE_BYTES 49152
#define SMEM_DYN (STAGES * STAGE_BYTES + 1024)

// ---------------- device scratch (no allocations allowed) ----------------
__device__ __nv_bfloat16 g_Xhi[NROWS * DDIM];
__device__ __nv_bfloat16 g_Xlo[NROWS * DDIM];
__device__ __nv_bfloat16 g_Yhi[NROWS * DDIM];
__device__ __nv_bfloat16 g_Ylo[NROWS * DDIM];
__device__ __nv_bfloat16 g_Bhi[4][DDIM * DDIM];   // B[n][k] = s_k * W[k][n], hi
__device__ __nv_bfloat16 g_Blo[4][DDIM * DDIM];
__device__ float g_bias [4][DDIM];                 // b'[n] = b[n] + sum_k t_k W[k][n]
__device__ float g_sum  [3 * DDIM];
__device__ float g_sumsq[3 * DDIM];
__device__ float g_scale[3 * DDIM];
__device__ float g_shift[3 * DDIM];

// ---------------- helpers ----------------
__device__ __forceinline__ uint32_t sm_u32(const void* p) {
    return (uint32_t)__cvta_generic_to_shared(p);
}
__device__ __forceinline__ float gelu_exact(float x) {
    return 0.5f * x * (1.0f + erff(x * 0.70710678118654752440f));
}
__device__ __forceinline__ void split2(float v, __nv_bfloat16& h, __nv_bfloat16& l) {
    h = __float2bfloat16(v);
    l = __float2bfloat16(v - __bfloat162float(h));
}
__device__ __forceinline__ uint32_t pack2(__nv_bfloat16 a, __nv_bfloat16 b) {
    __nv_bfloat162 t = __halves2bfloat162(a, b);
    return *reinterpret_cast<uint32_t*>(&t);
}
// SW64 swizzle for 64-byte rows (8-row x 64B atom)
__device__ __forceinline__ uint32_t swz64(uint32_t off) {
    return off ^ ((off >> 3) & 0x30);
}

#define CP16(sm, gp) \
    asm volatile("cp.async.cg.shared.global [%0], [%1], 16;" :: "r"(sm), "l"(gp) : "memory")
#define CP_COMMIT() asm volatile("cp.async.commit_group;" ::: "memory")
#define CP_WAITN(n) asm volatile("cp.async.wait_group %0;" :: "n"(n) : "memory")

#define LDSM_X4(r, addr) \
    asm volatile("ldmatrix.sync.aligned.m8n8.x4.shared.b16 {%0,%1,%2,%3}, [%4];" \
        : "=r"((r)[0]), "=r"((r)[1]), "=r"((r)[2]), "=r"((r)[3]) : "r"(addr))

__device__ __forceinline__ void mma16816(float* c, const uint32_t* a, uint32_t b0, uint32_t b1) {
    asm volatile(
        "mma.sync.aligned.m16n8k16.row.col.f32.bf16.bf16.f32 "
        "{%0,%1,%2,%3}, {%4,%5,%6,%7}, {%8,%9}, {%0,%1,%2,%3};"
        : "+f"(c[0]), "+f"(c[1]), "+f"(c[2]), "+f"(c[3])
        : "r"(a[0]), "r"(a[1]), "r"(a[2]), "r"(a[3]), "r"(b0), "r"(b1));
}

// ---------------- small kernels ----------------
__global__ void zero_stats_kernel() {
    int i = threadIdx.x;
    if (i < 3 * DDIM) { g_sum[i] = 0.f; g_sumsq[i] = 0.f; }
}

__global__ void finalize_stats_kernel(int layer, const float* __restrict__ g,
                                      const float* __restrict__ be) {
    int c = threadIdx.x;
    const float inv = 1.0f / (float)NROWS;
    float mu  = g_sum  [layer * DDIM + c] * inv;
    float var = g_sumsq[layer * DDIM + c] * inv - mu * mu;
    float s = rsqrtf(var + EPSV) * g[c];
    g_scale[layer * DDIM + c] = s;
    g_shift[layer * DDIM + c] = be[c] - mu * s;
}

__global__ void gather_split_kernel(const int* __restrict__ ids,
                                    const float* __restrict__ table) {
    int idx = blockIdx.x * blockDim.x + threadIdx.x;   // float4 index
    int row = idx >> 6;
    int q   = idx & 63;
    int src = ids[row];
    float4 v = reinterpret_cast<const float4*>(table + (size_t)src * DDIM)[q];
    __nv_bfloat16 h0, h1, h2, h3, l0, l1, l2, l3;
    split2(v.x, h0, l0); split2(v.y, h1, l1); split2(v.z, h2, l2); split2(v.w, h3, l3);
    reinterpret_cast<uint2*>(g_Xhi)[idx] = make_uint2(pack2(h0, h1), pack2(h2, h3));
    reinterpret_cast<uint2*>(g_Xlo)[idx] = make_uint2(pack2(l0, l1), pack2(l2, l3));
}

__global__ void prep_w_kernel(const float* __restrict__ W, const float* __restrict__ b,
                              int layer, int use_bn) {
    __shared__ float red[DDIM];
    int n = blockIdx.x, k = threadIdx.x;
    float w = W[k * DDIM + n];
    float s = 1.f, t = 0.f;
    if (use_bn) {
        s = g_scale[(layer - 1) * DDIM + k];
        t = g_shift[(layer - 1) * DDIM + k];
    }
    __nv_bfloat16 h, l;
    split2(w * s, h, l);
    g_Bhi[layer][n * DDIM + k] = h;
    g_Blo[layer][n * DDIM + k] = l;
    red[k] = t * w;
    __syncthreads();
    for (int st = 128; st > 0; st >>= 1) {
        if (k < st) red[k] += red[k + st];
        __syncthreads();
    }
    if (k == 0) g_bias[layer][n] = b[n] + red[0];
}

// ---------------- main fused GEMM layer (HMMA mma.sync, split-bf16 x3) ----------------
// CTA: M=128 x N=256, 16 warps (4M x 4N), warp tile 32x64.
// K chunks of 32, 4-stage cp.async pipeline, one barrier per chunk.
// MMAs ordered product-major: accumulator reuse distance 4 (breaks RAW chains).
template<int STATS, int FINAL>
__global__ __launch_bounds__(512, 1)
void gemm_kernel(const __nv_bfloat16* __restrict__ Ahi,
                 const __nv_bfloat16* __restrict__ Alo,
                 const __nv_bfloat16* __restrict__ Bhi,
                 const __nv_bfloat16* __restrict__ Blo,
                 const float* __restrict__ bias,
                 int layer,
                 float* __restrict__ outF,
                 __nv_bfloat16* __restrict__ outHi,
                 __nv_bfloat16* __restrict__ outLo)
{
    extern __shared__ char dyn_smem[];
    const int tid  = threadIdx.x;
    const int lane = tid & 31;
    const int wid  = tid >> 5;
    const int m_warp = (wid >> 2) * 32;
    const int n_warp = (wid & 3) * 64;
    const int r0 = blockIdx.x * 128;

    const uint32_t dyn0 = sm_u32(dyn_smem);
    const uint32_t su   = (dyn0 + 1023) & ~1023u;   // 1KB-aligned SMEM base

    float acc[2][8][4];
    #pragma unroll
    for (int i = 0; i < 2; i++)
        #pragma unroll
        for (int j = 0; j < 8; j++)
            #pragma unroll
            for (int q = 0; q < 4; q++) acc[i][j][q] = 0.f;

    // --- cp.async issue of one K-chunk (KC=32, 64B rows) into stage c%4 ---
    auto issue = [&](int c) {
        const uint32_t sb = su + (c & 3) * STAGE_BYTES;
        const int kt = c * KC;
        {   // A: 128 rows x 4 x 16B (hi+lo), 512 chunks per half, 1/thread
            int row = tid >> 2, q = tid & 3;
            uint32_t sw = swz64((uint32_t)(row * 64 + q * 16));
            const size_t g = (size_t)(r0 + row) * DDIM + kt + q * 8;
            CP16(sb + sw,        Ahi + g);
            CP16(sb + 8192 + sw, Alo + g);
        }
        #pragma unroll
        for (int i = 0; i < 2; i++) {   // B: 256 rows x 4 x 16B (hi+lo), 1024 per half
            int idx = tid + i * 512;
            int row = idx >> 2, q = idx & 3;
            uint32_t sw = swz64((uint32_t)(row * 64 + q * 16));
            const size_t g = (size_t)row * DDIM + kt + q * 8;
            CP16(sb + 16384 + sw, Bhi + g);
            CP16(sb + 32768 + sw, Blo + g);
        }
        CP_COMMIT();
    };

    // prologue: fill 3 stages
    issue(0); issue(1); issue(2);

    // A-frag lane addressing (row-major A, 16x16 frag = 4 m8n8)
    const uint32_t a_row = (uint32_t)(lane & 15);
    const uint32_t a_kh  = (uint32_t)(lane >> 4);
    // B-frag lane addressing (paired j/j+1 in one x4)
    const uint32_t b_row = (uint32_t)(((lane >> 4) & 1) * 8 + (lane & 7));
    const uint32_t b_kh  = (uint32_t)((lane >> 3) & 1);

    #pragma unroll
    for (int c = 0; c < NCHUNK; c++) {
        // wait for stage c data: pending newest allowed = issued_before - (c+1)
        if      (c <  NCHUNK - 2) CP_WAITN(2);
        else if (c == NCHUNK - 2) CP_WAITN(1);
        else                      CP_WAITN(0);
        __syncthreads();
        if (c + 3 < NCHUNK) issue(c + 3);

        const uint32_t sa = su + (c & 3) * STAGE_BYTES;
        #pragma unroll
        for (int ks = 0; ks < 2; ks++) {
            uint32_t a_hi[2][4], a_lo[2][4];
            #pragma unroll
            for (int i = 0; i < 2; i++) {
                uint32_t off = (m_warp + i * 16 + a_row) * 64 + ks * 32 + a_kh * 16;
                uint32_t ad = sa + swz64(off);
                LDSM_X4(a_hi[i], ad);
                LDSM_X4(a_lo[i], ad + 8192);
            }
            #pragma unroll
            for (int jp = 0; jp < 4; jp++) {
                uint32_t off = (n_warp + jp * 16 + b_row) * 64 + ks * 32 + b_kh * 16;
                uint32_t ad = sa + 16384 + swz64(off);
                uint32_t bh[4], bl[4];
                LDSM_X4(bh, ad);
                LDSM_X4(bl, ad + 16384);
                // product-major order: same accumulator reused only at distance 4
                mma16816(acc[0][2 * jp],     a_hi[0], bh[0], bh[1]);
                mma16816(acc[1][2 * jp],     a_hi[1], bh[0], bh[1]);
                mma16816(acc[0][2 * jp + 1], a_hi[0], bh[2], bh[3]);
                mma16816(acc[1][2 * jp + 1], a_hi[1], bh[2], bh[3]);
                mma16816(acc[0][2 * jp],     a_hi[0], bl[0], bl[1]);
                mma16816(acc[1][2 * jp],     a_hi[1], bl[0], bl[1]);
                mma16816(acc[0][2 * jp + 1], a_hi[0], bl[2], bl[3]);
                mma16816(acc[1][2 * jp + 1], a_hi[1], bl[2], bl[3]);
                mma16816(acc[0][2 * jp],     a_lo[0], bh[0], bh[1]);
                mma16816(acc[1][2 * jp],     a_lo[1], bh[0], bh[1]);
                mma16816(acc[0][2 * jp + 1], a_lo[0], bh[2], bh[3]);
                mma16816(acc[1][2 * jp + 1], a_lo[1], bh[2], bh[3]);
            }
        }
    }

    // ---- epilogue: bias + exact GELU + stores + column stats ----
    #pragma unroll
    for (int j = 0; j < 8; j++) {
        const int col0 = n_warp + j * 8 + (lane & 3) * 2;
        const float bi0 = bias[col0], bi1 = bias[col0 + 1];
        float su0 = 0.f, su1 = 0.f, sq0 = 0.f, sq1 = 0.f;
        #pragma unroll
        for (int i = 0; i < 2; i++) {
            const int rowA = r0 + m_warp + i * 16 + (lane >> 2);
            float v0 = gelu_exact(acc[i][j][0] + bi0);
            float v1 = gelu_exact(acc[i][j][1] + bi1);
            float v2 = gelu_exact(acc[i][j][2] + bi0);
            float v3 = gelu_exact(acc[i][j][3] + bi1);
            if (STATS) {
                su0 += v0 + v2; su1 += v1 + v3;
                sq0 += v0 * v0 + v2 * v2; sq1 += v1 * v1 + v3 * v3;
            }
            if (FINAL) {
                *reinterpret_cast<float2*>(outF + (size_t)rowA * DDIM + col0)
                    = make_float2(v0, v1);
                *reinterpret_cast<float2*>(outF + (size_t)(rowA + 8) * DDIM + col0)
                    = make_float2(v2, v3);
            } else {
                __nv_bfloat16 h0, l0, h1, l1;
                split2(v0, h0, l0); split2(v1, h1, l1);
                *reinterpret_cast<uint32_t*>(outHi + (size_t)rowA * DDIM + col0) = pack2(h0, h1);
                *reinterpret_cast<uint32_t*>(outLo + (size_t)rowA * DDIM + col0) = pack2(l0, l1);
                split2(v2, h0, l0); split2(v3, h1, l1);
                *reinterpret_cast<uint32_t*>(outHi + (size_t)(rowA + 8) * DDIM + col0) = pack2(h0, h1);
                *reinterpret_cast<uint32_t*>(outLo + (size_t)(rowA + 8) * DDIM + col0) = pack2(l0, l1);
            }
        }
        if (STATS) {
            #pragma unroll
            for (int m = 4; m <= 16; m <<= 1) {
                su0 += __shfl_xor_sync(0xFFFFFFFFu, su0, m);
                su1 += __shfl_xor_sync(0xFFFFFFFFu, su1, m);
                sq0 += __shfl_xor_sync(0xFFFFFFFFu, sq0, m);
                sq1 += __shfl_xor_sync(0xFFFFFFFFu, sq1, m);
            }
            if ((lane >> 2) == 0) {
                atomicAdd(&g_sum  [layer * DDIM + col0],     su0);
                atomicAdd(&g_sum  [layer * DDIM + col0 + 1], su1);
                atomicAdd(&g_sumsq[layer * DDIM + col0],     sq0);
                atomicAdd(&g_sumsq[layer * DDIM + col0 + 1], sq1);
            }
        }
    }
}

// ---------------- launch ----------------
extern "C" void kernel_launch(void* const* d_in, const int* in_sizes, int n_in,
                              void* d_out, int out_size) {
    const int*   ids   = (const int*)  d_in[0];
    const float* table = (const float*)d_in[1];
    const float* W[4]  = {(const float*)d_in[2], (const float*)d_in[4],
                          (const float*)d_in[6], (const float*)d_in[8]};
    const float* b[4]  = {(const float*)d_in[3], (const float*)d_in[5],
                          (const float*)d_in[7], (const float*)d_in[9]};
    const float* g[3]  = {(const float*)d_in[10], (const float*)d_in[12], (const float*)d_in[14]};
    const float* be[3] = {(const float*)d_in[11], (const float*)d_in[13], (const float*)d_in[15]};
    float* out = (float*)d_out;

    cudaFuncSetAttribute(gemm_kernel<1, 0>, cudaFuncAttributeMaxDynamicSharedMemorySize, SMEM_DYN);
    cudaFuncSetAttribute(gemm_kernel<0, 1>, cudaFuncAttributeMaxDynamicSharedMemorySize, SMEM_DYN);

    __nv_bfloat16 *Xhi, *Xlo, *Yhi, *Ylo, *Bh, *Bl;
    float *bs;
    cudaGetSymbolAddress((void**)&Xhi, g_Xhi);
    cudaGetSymbolAddress((void**)&Xlo, g_Xlo);
    cudaGetSymbolAddress((void**)&Yhi, g_Yhi);
    cudaGetSymbolAddress((void**)&Ylo, g_Ylo);
    cudaGetSymbolAddress((void**)&Bh,  g_Bhi);
    cudaGetSymbolAddress((void**)&Bl,  g_Blo);
    cudaGetSymbolAddress((void**)&bs,  g_bias);

    const dim3 grid(NROWS / 128), blk(512);

    zero_stats_kernel<<<1, 768>>>();
    gather_split_kernel<<<NROWS * DDIM / 4 / 256, 256>>>(ids, table);
    prep_w_kernel<<<DDIM, DDIM>>>(W[0], b[0], 0, 0);

    gemm_kernel<1, 0><<<grid, blk, SMEM_DYN>>>(
        Xhi, Xlo, Bh + 0 * DDIM * DDIM, Bl + 0 * DDIM * DDIM, bs + 0 * DDIM,
        0, nullptr, Yhi, Ylo);
    finalize_stats_kernel<<<1, DDIM>>>(0, g[0], be[0]);
    prep_w_kernel<<<DDIM, DDIM>>>(W[1], b[1], 1, 1);

    gemm_kernel<1, 0><<<grid, blk, SMEM_DYN>>>(
        Yhi, Ylo, Bh + 1 * DDIM * DDIM, Bl + 1 * DDIM * DDIM, bs + 1 * DDIM,
        1, nullptr, Xhi, Xlo);
    finalize_stats_kernel<<<1, DDIM>>>(1, g[1], be[1]);
    prep_w_kernel<<<DDIM, DDIM>>>(W[2], b[2], 2, 1);

    gemm_kernel<1, 0><<<grid, blk, SMEM_DYN>>>(
        Xhi, Xlo, Bh + 2 * DDIM * DDIM, Bl + 2 * DDIM * DDIM, bs + 2 * DDIM,
        2, nullptr, Yhi, Ylo);
    finalize_stats_kernel<<<1, DDIM>>>(2, g[2], be[2]);
    prep_w_kernel<<<DDIM, DDIM>>>(W[3], b[3], 3, 1);

    gemm_kernel<0, 1><<<grid, blk, SMEM_DYN>>>(
        Yhi, Ylo, Bh + 3 * DDIM * DDIM, Bl + 3 * DDIM * DDIM, bs + 3 * DDIM,
        3, out, nullptr, nullptr);
}

// round 7
// speedup vs baseline: 1.3352x; 1.3165x over previous
#include <cuda_runtime.h>
#include <cuda_fp16.h>
#include <math.h>
#include <stdint.h>

#define NROWS 32768
#define DDIM  256
#define EPSV  1e-5f
#define KC    32
#define NCHUNK 8
#define STAGES 4
// Stage: A 8K | Bhi 16K | Blo 16K = 40K
#define STAGE_BYTES 40960
#define SMEM_DYN (STAGES * STAGE_BYTES + 1024)

// ---------------- device scratch (no allocations allowed) ----------------
__device__ __half g_X[NROWS * DDIM];
__device__ __half g_Y[NROWS * DDIM];
__device__ __half g_Bhi[4][DDIM * DDIM];   // B[n][k] = s_k * W[k][n], fp16 hi
__device__ __half g_Blo[4][DDIM * DDIM];   // fp16 residual
__device__ float g_bias [4][DDIM];          // b'[n] = b[n] + sum_k t_k W[k][n]
__device__ float g_sum  [3 * DDIM];
__device__ float g_sumsq[3 * DDIM];
__device__ float g_scale[3 * DDIM];
__device__ float g_shift[3 * DDIM];

// ---------------- helpers ----------------
__device__ __forceinline__ uint32_t sm_u32(const void* p) {
    return (uint32_t)__cvta_generic_to_shared(p);
}
__device__ __forceinline__ float gelu_exact(float x) {
    return 0.5f * x * (1.0f + erff(x * 0.70710678118654752440f));
}
__device__ __forceinline__ void split2h(float v, __half& h, __half& l) {
    h = __float2half(v);
    l = __float2half(v - __half2float(h));
}
__device__ __forceinline__ uint32_t pack2h(__half a, __half b) {
    __half2 t = __halves2half2(a, b);
    return *reinterpret_cast<uint32_t*>(&t);
}
// SW64 swizzle for 64-byte rows (8-row x 64B atom)
__device__ __forceinline__ uint32_t swz64(uint32_t off) {
    return off ^ ((off >> 3) & 0x30);
}

#define CP16(sm, gp) \
    asm volatile("cp.async.cg.shared.global [%0], [%1], 16;" :: "r"(sm), "l"(gp) : "memory")
#define CP_COMMIT() asm volatile("cp.async.commit_group;" ::: "memory")
#define CP_WAITN(n) asm volatile("cp.async.wait_group %0;" :: "n"(n) : "memory")

#define LDSM_X4(r, addr) \
    asm volatile("ldmatrix.sync.aligned.m8n8.x4.shared.b16 {%0,%1,%2,%3}, [%4];" \
        : "=r"((r)[0]), "=r"((r)[1]), "=r"((r)[2]), "=r"((r)[3]) : "r"(addr))

__device__ __forceinline__ void mma16816(float* c, const uint32_t* a, uint32_t b0, uint32_t b1) {
    asm volatile(
        "mma.sync.aligned.m16n8k16.row.col.f32.f16.f16.f32 "
        "{%0,%1,%2,%3}, {%4,%5,%6,%7}, {%8,%9}, {%0,%1,%2,%3};"
        : "+f"(c[0]), "+f"(c[1]), "+f"(c[2]), "+f"(c[3])
        : "r"(a[0]), "r"(a[1]), "r"(a[2]), "r"(a[3]), "r"(b0), "r"(b1));
}

// ---------------- small kernels ----------------
__global__ void zero_stats_kernel() {
    int i = threadIdx.x;
    if (i < 3 * DDIM) { g_sum[i] = 0.f; g_sumsq[i] = 0.f; }
}

__global__ void finalize_stats_kernel(int layer, const float* __restrict__ g,
                                      const float* __restrict__ be) {
    int c = threadIdx.x;
    const float inv = 1.0f / (float)NROWS;
    float mu  = g_sum  [layer * DDIM + c] * inv;
    float var = g_sumsq[layer * DDIM + c] * inv - mu * mu;
    float s = rsqrtf(var + EPSV) * g[c];
    g_scale[layer * DDIM + c] = s;
    g_shift[layer * DDIM + c] = be[c] - mu * s;
}

__global__ void gather_split_kernel(const int* __restrict__ ids,
                                    const float* __restrict__ table) {
    int idx = blockIdx.x * blockDim.x + threadIdx.x;   // float4 index
    int row = idx >> 6;
    int q   = idx & 63;
    int src = ids[row];
    float4 v = reinterpret_cast<const float4*>(table + (size_t)src * DDIM)[q];
    uint2 o;
    o.x = pack2h(__float2half(v.x), __float2half(v.y));
    o.y = pack2h(__float2half(v.z), __float2half(v.w));
    reinterpret_cast<uint2*>(g_X)[idx] = o;
}

__global__ void prep_w_kernel(const float* __restrict__ W, const float* __restrict__ b,
                              int layer, int use_bn) {
    __shared__ float red[DDIM];
    int n = blockIdx.x, k = threadIdx.x;
    float w = W[k * DDIM + n];
    float s = 1.f, t = 0.f;
    if (use_bn) {
        s = g_scale[(layer - 1) * DDIM + k];
        t = g_shift[(layer - 1) * DDIM + k];
    }
    __half h, l;
    split2h(w * s, h, l);
    g_Bhi[layer][n * DDIM + k] = h;
    g_Blo[layer][n * DDIM + k] = l;
    red[k] = t * w;
    __syncthreads();
    for (int st = 128; st > 0; st >>= 1) {
        if (k < st) red[k] += red[k + st];
        __syncthreads();
    }
    if (k == 0) g_bias[layer][n] = b[n] + red[0];
}

// ---------------- main fused GEMM layer (HMMA fp16, A-single x B-split, 2 products) ----
// CTA: M=128 x N=256, 16 warps (4M x 4N), warp tile 32x64.
// K chunks of 32, 4-stage cp.async pipeline, one barrier per chunk.
template<int STATS, int FINAL>
__global__ __launch_bounds__(512, 1)
void gemm_kernel(const __half* __restrict__ A,
                 const __half* __restrict__ Bhi,
                 const __half* __restrict__ Blo,
                 const float* __restrict__ bias,
                 int layer,
                 float* __restrict__ outF,
                 __half* __restrict__ outH)
{
    extern __shared__ char dyn_smem[];
    const int tid  = threadIdx.x;
    const int lane = tid & 31;
    const int wid  = tid >> 5;
    const int m_warp = (wid >> 2) * 32;
    const int n_warp = (wid & 3) * 64;
    const int r0 = blockIdx.x * 128;

    const uint32_t dyn0 = sm_u32(dyn_smem);
    const uint32_t su   = (dyn0 + 1023) & ~1023u;   // 1KB-aligned SMEM base

    float acc[2][8][4];
    #pragma unroll
    for (int i = 0; i < 2; i++)
        #pragma unroll
        for (int j = 0; j < 8; j++)
            #pragma unroll
            for (int q = 0; q < 4; q++) acc[i][j][q] = 0.f;

    // --- cp.async issue of one K-chunk (KC=32, 64B rows) into stage c%4 ---
    auto issue = [&](int c) {
        const uint32_t sb = su + (c & 3) * STAGE_BYTES;
        const int kt = c * KC;
        {   // A: 128 rows x 4 x 16B = 512 chunks, 1/thread
            int row = tid >> 2, q = tid & 3;
            uint32_t sw = swz64((uint32_t)(row * 64 + q * 16));
            CP16(sb + sw, A + (size_t)(r0 + row) * DDIM + kt + q * 8);
        }
        #pragma unroll
        for (int i = 0; i < 2; i++) {   // Bhi/Blo: 256 rows x 4 x 16B = 1024 each
            int idx = tid + i * 512;
            int row = idx >> 2, q = idx & 3;
            uint32_t sw = swz64((uint32_t)(row * 64 + q * 16));
            const size_t g = (size_t)row * DDIM + kt + q * 8;
            CP16(sb + 8192 + sw,  Bhi + g);
            CP16(sb + 24576 + sw, Blo + g);
        }
        CP_COMMIT();
    };

    // prologue: fill 3 stages
    issue(0); issue(1); issue(2);

    // A-frag lane addressing (row-major A, 16x16 frag = 4 m8n8)
    const uint32_t a_row = (uint32_t)(lane & 15);
    const uint32_t a_kh  = (uint32_t)(lane >> 4);
    // B-frag lane addressing (paired j/j+1 in one x4)
    const uint32_t b_row = (uint32_t)(((lane >> 4) & 1) * 8 + (lane & 7));
    const uint32_t b_kh  = (uint32_t)((lane >> 3) & 1);

    #pragma unroll
    for (int c = 0; c < NCHUNK; c++) {
        if      (c <  NCHUNK - 2) CP_WAITN(2);
        else if (c == NCHUNK - 2) CP_WAITN(1);
        else                      CP_WAITN(0);
        __syncthreads();
        if (c + 3 < NCHUNK) issue(c + 3);

        const uint32_t sa = su + (c & 3) * STAGE_BYTES;
        #pragma unroll
        for (int ks = 0; ks < 2; ks++) {
            uint32_t a_f[2][4];
            #pragma unroll
            for (int i = 0; i < 2; i++) {
                uint32_t off = (m_warp + i * 16 + a_row) * 64 + ks * 32 + a_kh * 16;
                LDSM_X4(a_f[i], sa + swz64(off));
            }
            #pragma unroll
            for (int jp = 0; jp < 4; jp++) {
                uint32_t off = (n_warp + jp * 16 + b_row) * 64 + ks * 32 + b_kh * 16;
                uint32_t ad = sa + 8192 + swz64(off);
                uint32_t bh[4], bl[4];
                LDSM_X4(bh, ad);
                LDSM_X4(bl, ad + 16384);
                // product-major: same accumulator reused at distance 4
                mma16816(acc[0][2 * jp],     a_f[0], bh[0], bh[1]);
                mma16816(acc[1][2 * jp],     a_f[1], bh[0], bh[1]);
                mma16816(acc[0][2 * jp + 1], a_f[0], bh[2], bh[3]);
                mma16816(acc[1][2 * jp + 1], a_f[1], bh[2], bh[3]);
                mma16816(acc[0][2 * jp],     a_f[0], bl[0], bl[1]);
                mma16816(acc[1][2 * jp],     a_f[1], bl[0], bl[1]);
                mma16816(acc[0][2 * jp + 1], a_f[0], bl[2], bl[3]);
                mma16816(acc[1][2 * jp + 1], a_f[1], bl[2], bl[3]);
            }
        }
    }

    // ---- epilogue: bias + exact GELU + stores + column stats ----
    #pragma unroll
    for (int j = 0; j < 8; j++) {
        const int col0 = n_warp + j * 8 + (lane & 3) * 2;
        const float bi0 = bias[col0], bi1 = bias[col0 + 1];
        float su0 = 0.f, su1 = 0.f, sq0 = 0.f, sq1 = 0.f;
        #pragma unroll
        for (int i = 0; i < 2; i++) {
            const int rowA = r0 + m_warp + i * 16 + (lane >> 2);
            float v0 = gelu_exact(acc[i][j][0] + bi0);
            float v1 = gelu_exact(acc[i][j][1] + bi1);
            float v2 = gelu_exact(acc[i][j][2] + bi0);
            float v3 = gelu_exact(acc[i][j][3] + bi1);
            if (STATS) {
                su0 += v0 + v2; su1 += v1 + v3;
                sq0 += v0 * v0 + v2 * v2; sq1 += v1 * v1 + v3 * v3;
            }
            if (FINAL) {
                *reinterpret_cast<float2*>(outF + (size_t)rowA * DDIM + col0)
                    = make_float2(v0, v1);
                *reinterpret_cast<float2*>(outF + (size_t)(rowA + 8) * DDIM + col0)
                    = make_float2(v2, v3);
            } else {
                *reinterpret_cast<uint32_t*>(outH + (size_t)rowA * DDIM + col0)
                    = pack2h(__float2half(v0), __float2half(v1));
                *reinterpret_cast<uint32_t*>(outH + (size_t)(rowA + 8) * DDIM + col0)
                    = pack2h(__float2half(v2), __float2half(v3));
            }
        }
        if (STATS) {
            #pragma unroll
            for (int m = 4; m <= 16; m <<= 1) {
                su0 += __shfl_xor_sync(0xFFFFFFFFu, su0, m);
                su1 += __shfl_xor_sync(0xFFFFFFFFu, su1, m);
                sq0 += __shfl_xor_sync(0xFFFFFFFFu, sq0, m);
                sq1 += __shfl_xor_sync(0xFFFFFFFFu, sq1, m);
            }
            if ((lane >> 2) == 0) {
                atomicAdd(&g_sum  [layer * DDIM + col0],     su0);
                atomicAdd(&g_sum  [layer * DDIM + col0 + 1], su1);
                atomicAdd(&g_sumsq[layer * DDIM + col0],     sq0);
                atomicAdd(&g_sumsq[layer * DDIM + col0 + 1], sq1);
            }
        }
    }
}

// ---------------- launch ----------------
extern "C" void kernel_launch(void* const* d_in, const int* in_sizes, int n_in,
                              void* d_out, int out_size) {
    const int*   ids   = (const int*)  d_in[0];
    const float* table = (const float*)d_in[1];
    const float* W[4]  = {(const float*)d_in[2], (const float*)d_in[4],
                          (const float*)d_in[6], (const float*)d_in[8]};
    const float* b[4]  = {(const float*)d_in[3], (const float*)d_in[5],
                          (const float*)d_in[7], (const float*)d_in[9]};
    const float* g[3]  = {(const float*)d_in[10], (const float*)d_in[12], (const float*)d_in[14]};
    const float* be[3] = {(const float*)d_in[11], (const float*)d_in[13], (const float*)d_in[15]};
    float* out = (float*)d_out;

    cudaFuncSetAttribute(gemm_kernel<1, 0>, cudaFuncAttributeMaxDynamicSharedMemorySize, SMEM_DYN);
    cudaFuncSetAttribute(gemm_kernel<0, 1>, cudaFuncAttributeMaxDynamicSharedMemorySize, SMEM_DYN);

    __half *X, *Y, *Bh, *Bl;
    float *bs;
    cudaGetSymbolAddress((void**)&X,  g_X);
    cudaGetSymbolAddress((void**)&Y,  g_Y);
    cudaGetSymbolAddress((void**)&Bh, g_Bhi);
    cudaGetSymbolAddress((void**)&Bl, g_Blo);
    cudaGetSymbolAddress((void**)&bs, g_bias);

    const dim3 grid(NROWS / 128), blk(512);

    zero_stats_kernel<<<1, 768>>>();
    gather_split_kernel<<<NROWS * DDIM / 4 / 256, 256>>>(ids, table);
    prep_w_kernel<<<DDIM, DDIM>>>(W[0], b[0], 0, 0);

    gemm_kernel<1, 0><<<grid, blk, SMEM_DYN>>>(
        X, Bh + 0 * DDIM * DDIM, Bl + 0 * DDIM * DDIM, bs + 0 * DDIM,
        0, nullptr, Y);
    finalize_stats_kernel<<<1, DDIM>>>(0, g[0], be[0]);
    prep_w_kernel<<<DDIM, DDIM>>>(W[1], b[1], 1, 1);

    gemm_kernel<1, 0><<<grid, blk, SMEM_DYN>>>(
        Y, Bh + 1 * DDIM * DDIM, Bl + 1 * DDIM * DDIM, bs + 1 * DDIM,
        1, nullptr, X);
    finalize_stats_kernel<<<1, DDIM>>>(1, g[1], be[1]);
    prep_w_kernel<<<DDIM, DDIM>>>(W[2], b[2], 2, 1);

    gemm_kernel<1, 0><<<grid, blk, SMEM_DYN>>>(
        X, Bh + 2 * DDIM * DDIM, Bl + 2 * DDIM * DDIM, bs + 2 * DDIM,
        2, nullptr, Y);
    finalize_stats_kernel<<<1, DDIM>>>(2, g[2], be[2]);
    prep_w_kernel<<<DDIM, DDIM>>>(W[3], b[3], 3, 1);

    gemm_kernel<0, 1><<<grid, blk, SMEM_DYN>>>(
        Y, Bh + 3 * DDIM * DDIM, Bl + 3 * DDIM * DDIM, bs + 3 * DDIM,
        3, out, nullptr);
}

// round 8
// speedup vs baseline: 1.5115x; 1.1320x over previous
#include <cuda_runtime.h>
#include <cuda_fp16.h>
#include <math.h>
#include <stdint.h>

#define NROWS 32768
#define DDIM  256
#define EPSV  1e-5f
#define KC    32
#define NCHUNK 8
#define STAGES 4
// Stage: A 8K | Bhi 8K | Blo 8K = 24K
#define STAGE_BYTES 24576
#define SMEM_DYN (STAGES * STAGE_BYTES + 1024)

// ---------------- device scratch (no allocations allowed) ----------------
__device__ __half g_X[NROWS * DDIM];
__device__ __half g_Y[NROWS * DDIM];
__device__ __half g_Bhi[4][DDIM * DDIM];   // B[n][k] = s_k * W[k][n], fp16 hi
__device__ __half g_Blo[4][DDIM * DDIM];   // fp16 residual
__device__ float g_bias [4][DDIM];          // b'[n] = b[n] + sum_k t_k W[k][n]
__device__ float g_sum  [3 * DDIM];
__device__ float g_sumsq[3 * DDIM];
__device__ float g_scale[3 * DDIM];
__device__ float g_shift[3 * DDIM];

// ---------------- helpers ----------------
__device__ __forceinline__ uint32_t sm_u32(const void* p) {
    return (uint32_t)__cvta_generic_to_shared(p);
}
__device__ __forceinline__ float gelu_exact(float x) {
    return 0.5f * x * (1.0f + erff(x * 0.70710678118654752440f));
}
__device__ __forceinline__ void split2h(float v, __half& h, __half& l) {
    h = __float2half(v);
    l = __float2half(v - __half2float(h));
}
__device__ __forceinline__ uint32_t pack2h(__half a, __half b) {
    __half2 t = __halves2half2(a, b);
    return *reinterpret_cast<uint32_t*>(&t);
}
// SW64 swizzle for 64-byte rows (8-row x 64B atom)
__device__ __forceinline__ uint32_t swz64(uint32_t off) {
    return off ^ ((off >> 3) & 0x30);
}

#define CP16(sm, gp) \
    asm volatile("cp.async.cg.shared.global [%0], [%1], 16;" :: "r"(sm), "l"(gp) : "memory")
#define CP_COMMIT() asm volatile("cp.async.commit_group;" ::: "memory")
#define CP_WAITN(n) asm volatile("cp.async.wait_group %0;" :: "n"(n) : "memory")

#define LDSM_X4(r, addr) \
    asm volatile("ldmatrix.sync.aligned.m8n8.x4.shared.b16 {%0,%1,%2,%3}, [%4];" \
        : "=r"((r)[0]), "=r"((r)[1]), "=r"((r)[2]), "=r"((r)[3]) : "r"(addr))

__device__ __forceinline__ void mma16816(float* c, const uint32_t* a, uint32_t b0, uint32_t b1) {
    asm volatile(
        "mma.sync.aligned.m16n8k16.row.col.f32.f16.f16.f32 "
        "{%0,%1,%2,%3}, {%4,%5,%6,%7}, {%8,%9}, {%0,%1,%2,%3};"
        : "+f"(c[0]), "+f"(c[1]), "+f"(c[2]), "+f"(c[3])
        : "r"(a[0]), "r"(a[1]), "r"(a[2]), "r"(a[3]), "r"(b0), "r"(b1));
}

// ---------------- small kernels ----------------
__global__ void zero_stats_kernel() {
    int i = threadIdx.x;
    if (i < 3 * DDIM) { g_sum[i] = 0.f; g_sumsq[i] = 0.f; }
}

__global__ void finalize_stats_kernel(int layer, const float* __restrict__ g,
                                      const float* __restrict__ be) {
    int c = threadIdx.x;
    const float inv = 1.0f / (float)NROWS;
    float mu  = g_sum  [layer * DDIM + c] * inv;
    float var = g_sumsq[layer * DDIM + c] * inv - mu * mu;
    float s = rsqrtf(var + EPSV) * g[c];
    g_scale[layer * DDIM + c] = s;
    g_shift[layer * DDIM + c] = be[c] - mu * s;
}

__global__ void gather_split_kernel(const int* __restrict__ ids,
                                    const float* __restrict__ table) {
    int idx = blockIdx.x * blockDim.x + threadIdx.x;   // float4 index
    int row = idx >> 6;
    int q   = idx & 63;
    int src = ids[row];
    float4 v = reinterpret_cast<const float4*>(table + (size_t)src * DDIM)[q];
    uint2 o;
    o.x = pack2h(__float2half(v.x), __float2half(v.y));
    o.y = pack2h(__float2half(v.z), __float2half(v.w));
    reinterpret_cast<uint2*>(g_X)[idx] = o;
}

__global__ void prep_w_kernel(const float* __restrict__ W, const float* __restrict__ b,
                              int layer, int use_bn) {
    __shared__ float red[DDIM];
    int n = blockIdx.x, k = threadIdx.x;
    float w = W[k * DDIM + n];
    float s = 1.f, t = 0.f;
    if (use_bn) {
        s = g_scale[(layer - 1) * DDIM + k];
        t = g_shift[(layer - 1) * DDIM + k];
    }
    __half h, l;
    split2h(w * s, h, l);
    g_Bhi[layer][n * DDIM + k] = h;
    g_Blo[layer][n * DDIM + k] = l;
    red[k] = t * w;
    __syncthreads();
    for (int st = 128; st > 0; st >>= 1) {
        if (k < st) red[k] += red[k + st];
        __syncthreads();
    }
    if (k == 0) g_bias[layer][n] = b[n] + red[0];
}

// ---------------- main fused GEMM layer (HMMA fp16, A-single x B-split, 2 products) ----
// CTA: M=128 x N=128, 8 warps (4M x 2N), warp tile 32x64, 2 CTAs/SM.
// K chunks of 32, 4-stage cp.async pipeline, one barrier per chunk.
template<int STATS, int FINAL>
__global__ __launch_bounds__(256, 2)
void gemm_kernel(const __half* __restrict__ A,
                 const __half* __restrict__ Bhi,
                 const __half* __restrict__ Blo,
                 const float* __restrict__ bias,
                 int layer,
                 float* __restrict__ outF,
                 __half* __restrict__ outH)
{
    extern __shared__ char dyn_smem[];
    const int tid  = threadIdx.x;
    const int lane = tid & 31;
    const int wid  = tid >> 5;
    const int m_warp = (wid >> 1) * 32;          // 4 M-groups
    const int n_warp = (wid & 1) * 64;           // 2 N-groups
    const int r0 = blockIdx.x * 128;
    const int c0 = blockIdx.y * 128;

    const uint32_t dyn0 = sm_u32(dyn_smem);
    const uint32_t su   = (dyn0 + 1023) & ~1023u;   // 1KB-aligned SMEM base

    float acc[2][8][4];
    #pragma unroll
    for (int i = 0; i < 2; i++)
        #pragma unroll
        for (int j = 0; j < 8; j++)
            #pragma unroll
            for (int q = 0; q < 4; q++) acc[i][j][q] = 0.f;

    // --- cp.async issue of one K-chunk (KC=32, 64B rows) into stage c%4 ---
    auto issue = [&](int c) {
        const uint32_t sb = su + (c & 3) * STAGE_BYTES;
        const int kt = c * KC;
        #pragma unroll
        for (int i = 0; i < 2; i++) {   // A: 128 rows x 4 x 16B = 512 chunks
            int idx = tid + i * 256;
            int row = idx >> 2, q = idx & 3;
            uint32_t sw = swz64((uint32_t)(row * 64 + q * 16));
            CP16(sb + sw, A + (size_t)(r0 + row) * DDIM + kt + q * 8);
        }
        #pragma unroll
        for (int i = 0; i < 2; i++) {   // Bhi/Blo: 128 rows x 4 x 16B = 512 each
            int idx = tid + i * 256;
            int row = idx >> 2, q = idx & 3;
            uint32_t sw = swz64((uint32_t)(row * 64 + q * 16));
            const size_t g = (size_t)(c0 + row) * DDIM + kt + q * 8;
            CP16(sb + 8192 + sw,  Bhi + g);
            CP16(sb + 16384 + sw, Blo + g);
        }
        CP_COMMIT();
    };

    // prologue: fill 3 stages
    issue(0); issue(1); issue(2);

    // A-frag lane addressing (row-major A, 16x16 frag = 4 m8n8)
    const uint32_t a_row = (uint32_t)(lane & 15);
    const uint32_t a_kh  = (uint32_t)(lane >> 4);
    // B-frag lane addressing (paired j/j+1 in one x4)
    const uint32_t b_row = (uint32_t)(((lane >> 4) & 1) * 8 + (lane & 7));
    const uint32_t b_kh  = (uint32_t)((lane >> 3) & 1);

    #pragma unroll
    for (int c = 0; c < NCHUNK; c++) {
        if      (c <  NCHUNK - 2) CP_WAITN(2);
        else if (c == NCHUNK - 2) CP_WAITN(1);
        else                      CP_WAITN(0);
        __syncthreads();
        if (c + 3 < NCHUNK) issue(c + 3);

        const uint32_t sa = su + (c & 3) * STAGE_BYTES;
        #pragma unroll
        for (int ks = 0; ks < 2; ks++) {
            uint32_t a_f[2][4];
            #pragma unroll
            for (int i = 0; i < 2; i++) {
                uint32_t off = (m_warp + i * 16 + a_row) * 64 + ks * 32 + a_kh * 16;
                LDSM_X4(a_f[i], sa + swz64(off));
            }
            #pragma unroll
            for (int jp = 0; jp < 4; jp++) {
                uint32_t off = (n_warp + jp * 16 + b_row) * 64 + ks * 32 + b_kh * 16;
                uint32_t ad = sa + 8192 + swz64(off);
                uint32_t bh[4], bl[4];
                LDSM_X4(bh, ad);
                LDSM_X4(bl, ad + 8192);
                // product-major: same accumulator reused at distance 4
                mma16816(acc[0][2 * jp],     a_f[0], bh[0], bh[1]);
                mma16816(acc[1][2 * jp],     a_f[1], bh[0], bh[1]);
                mma16816(acc[0][2 * jp + 1], a_f[0], bh[2], bh[3]);
                mma16816(acc[1][2 * jp + 1], a_f[1], bh[2], bh[3]);
                mma16816(acc[0][2 * jp],     a_f[0], bl[0], bl[1]);
                mma16816(acc[1][2 * jp],     a_f[1], bl[0], bl[1]);
                mma16816(acc[0][2 * jp + 1], a_f[0], bl[2], bl[3]);
                mma16816(acc[1][2 * jp + 1], a_f[1], bl[2], bl[3]);
            }
        }
    }

    // ---- epilogue: bias + exact GELU + stores + column stats ----
    #pragma unroll
    for (int j = 0; j < 8; j++) {
        const int colL = n_warp + j * 8 + (lane & 3) * 2;   // 0..127 in CTA
        const int col0 = c0 + colL;                          // global column
        const float bi0 = bias[col0], bi1 = bias[col0 + 1];
        float su0 = 0.f, su1 = 0.f, sq0 = 0.f, sq1 = 0.f;
        #pragma unroll
        for (int i = 0; i < 2; i++) {
            const int rowA = r0 + m_warp + i * 16 + (lane >> 2);
            float v0 = gelu_exact(acc[i][j][0] + bi0);
            float v1 = gelu_exact(acc[i][j][1] + bi1);
            float v2 = gelu_exact(acc[i][j][2] + bi0);
            float v3 = gelu_exact(acc[i][j][3] + bi1);
            if (STATS) {
                su0 += v0 + v2; su1 += v1 + v3;
                sq0 += v0 * v0 + v2 * v2; sq1 += v1 * v1 + v3 * v3;
            }
            if (FINAL) {
                *reinterpret_cast<float2*>(outF + (size_t)rowA * DDIM + col0)
                    = make_float2(v0, v1);
                *reinterpret_cast<float2*>(outF + (size_t)(rowA + 8) * DDIM + col0)
                    = make_float2(v2, v3);
            } else {
                *reinterpret_cast<uint32_t*>(outH + (size_t)rowA * DDIM + col0)
                    = pack2h(__float2half(v0), __float2half(v1));
                *reinterpret_cast<uint32_t*>(outH + (size_t)(rowA + 8) * DDIM + col0)
                    = pack2h(__float2half(v2), __float2half(v3));
            }
        }
        if (STATS) {
            #pragma unroll
            for (int m = 4; m <= 16; m <<= 1) {
                su0 += __shfl_xor_sync(0xFFFFFFFFu, su0, m);
                su1 += __shfl_xor_sync(0xFFFFFFFFu, su1, m);
                sq0 += __shfl_xor_sync(0xFFFFFFFFu, sq0, m);
                sq1 += __shfl_xor_sync(0xFFFFFFFFu, sq1, m);
            }
            if ((lane >> 2) == 0) {
                atomicAdd(&g_sum  [layer * DDIM + col0],     su0);
                atomicAdd(&g_sum  [layer * DDIM + col0 + 1], su1);
                atomicAdd(&g_sumsq[layer * DDIM + col0],     sq0);
                atomicAdd(&g_sumsq[layer * DDIM + col0 + 1], sq1);
            }
        }
    }
}

// ---------------- launch ----------------
extern "C" void kernel_launch(void* const* d_in, const int* in_sizes, int n_in,
                              void* d_out, int out_size) {
    const int*   ids   = (const int*)  d_in[0];
    const float* table = (const float*)d_in[1];
    const float* W[4]  = {(const float*)d_in[2], (const float*)d_in[4],
                          (const float*)d_in[6], (const float*)d_in[8]};
    const float* b[4]  = {(const float*)d_in[3], (const float*)d_in[5],
                          (const float*)d_in[7], (const float*)d_in[9]};
    const float* g[3]  = {(const float*)d_in[10], (const float*)d_in[12], (const float*)d_in[14]};
    const float* be[3] = {(const float*)d_in[11], (const float*)d_in[13], (const float*)d_in[15]};
    float* out = (float*)d_out;

    cudaFuncSetAttribute(gemm_kernel<1, 0>, cudaFuncAttributeMaxDynamicSharedMemorySize, SMEM_DYN);
    cudaFuncSetAttribute(gemm_kernel<0, 1>, cudaFuncAttributeMaxDynamicSharedMemorySize, SMEM_DYN);

    __half *X, *Y, *Bh, *Bl;
    float *bs;
    cudaGetSymbolAddress((void**)&X,  g_X);
    cudaGetSymbolAddress((void**)&Y,  g_Y);
    cudaGetSymbolAddress((void**)&Bh, g_Bhi);
    cudaGetSymbolAddress((void**)&Bl, g_Blo);
    cudaGetSymbolAddress((void**)&bs, g_bias);

    const dim3 grid(NROWS / 128, DDIM / 128), blk(256);

    zero_stats_kernel<<<1, 768>>>();
    gather_split_kernel<<<NROWS * DDIM / 4 / 256, 256>>>(ids, table);
    prep_w_kernel<<<DDIM, DDIM>>>(W[0], b[0], 0, 0);

    gemm_kernel<1, 0><<<grid, blk, SMEM_DYN>>>(
        X, Bh + 0 * DDIM * DDIM, Bl + 0 * DDIM * DDIM, bs + 0 * DDIM,
        0, nullptr, Y);
    finalize_stats_kernel<<<1, DDIM>>>(0, g[0], be[0]);
    prep_w_kernel<<<DDIM, DDIM>>>(W[1], b[1], 1, 1);

    gemm_kernel<1, 0><<<grid, blk, SMEM_DYN>>>(
        Y, Bh + 1 * DDIM * DDIM, Bl + 1 * DDIM * DDIM, bs + 1 * DDIM,
        1, nullptr, X);
    finalize_stats_kernel<<<1, DDIM>>>(1, g[1], be[1]);
    prep_w_kernel<<<DDIM, DDIM>>>(W[2], b[2], 2, 1);

    gemm_kernel<1, 0><<<grid, blk, SMEM_DYN>>>(
        X, Bh + 2 * DDIM * DDIM, Bl + 2 * DDIM * DDIM, bs + 2 * DDIM,
        2, nullptr, Y);
    finalize_stats_kernel<<<1, DDIM>>>(2, g[2], be[2]);
    prep_w_kernel<<<DDIM, DDIM>>>(W[3], b[3], 3, 1);

    gemm_kernel<0, 1><<<grid, blk, SMEM_DYN>>>(
        Y, Bh + 3 * DDIM * DDIM, Bl + 3 * DDIM * DDIM, bs + 3 * DDIM,
        3, out, nullptr);
}

// round 9
// speedup vs baseline: 1.5283x; 1.0111x over previous
#include <cuda_runtime.h>
#include <cuda_fp16.h>
#include <math.h>
#include <stdint.h>

#define NROWS 32768
#define DDIM  256
#define EPSV  1e-5f
#define KC    32
#define NCHUNK 8
#define STAGES 2
// Stage: A 4K | Bhi 8K | Blo 8K = 20K
#define STAGE_BYTES 20480
#define SMEM_DYN (STAGES * STAGE_BYTES + 1024)

// ---------------- device scratch (no allocations allowed) ----------------
__device__ __half g_X[NROWS * DDIM];
__device__ __half g_Y[NROWS * DDIM];
__device__ __half g_Bhi[4][DDIM * DDIM];   // B[n][k] = s_k * W[k][n], fp16 hi
__device__ __half g_Blo[4][DDIM * DDIM];   // fp16 residual
__device__ float g_bias [4][DDIM];          // b'[n] = b[n] + sum_k t_k W[k][n]
__device__ float g_sum  [3 * DDIM];
__device__ float g_sumsq[3 * DDIM];
__device__ float g_scale[3 * DDIM];
__device__ float g_shift[3 * DDIM];

// ---------------- helpers ----------------
__device__ __forceinline__ uint32_t sm_u32(const void* p) {
    return (uint32_t)__cvta_generic_to_shared(p);
}
__device__ __forceinline__ float gelu_exact(float x) {
    return 0.5f * x * (1.0f + erff(x * 0.70710678118654752440f));
}
__device__ __forceinline__ void split2h(float v, __half& h, __half& l) {
    h = __float2half(v);
    l = __float2half(v - __half2float(h));
}
__device__ __forceinline__ uint32_t pack2h(__half a, __half b) {
    __half2 t = __halves2half2(a, b);
    return *reinterpret_cast<uint32_t*>(&t);
}
// SW64 swizzle for 64-byte rows (8-row x 64B atom)
__device__ __forceinline__ uint32_t swz64(uint32_t off) {
    return off ^ ((off >> 3) & 0x30);
}

#define CP16(sm, gp) \
    asm volatile("cp.async.cg.shared.global [%0], [%1], 16;" :: "r"(sm), "l"(gp) : "memory")
#define CP_COMMIT() asm volatile("cp.async.commit_group;" ::: "memory")
#define CP_WAITN(n) asm volatile("cp.async.wait_group %0;" :: "n"(n) : "memory")

#define LDSM_X4(r, addr) \
    asm volatile("ldmatrix.sync.aligned.m8n8.x4.shared.b16 {%0,%1,%2,%3}, [%4];" \
        : "=r"((r)[0]), "=r"((r)[1]), "=r"((r)[2]), "=r"((r)[3]) : "r"(addr))

__device__ __forceinline__ void mma16816(float* c, const uint32_t* a, uint32_t b0, uint32_t b1) {
    asm volatile(
        "mma.sync.aligned.m16n8k16.row.col.f32.f16.f16.f32 "
        "{%0,%1,%2,%3}, {%4,%5,%6,%7}, {%8,%9}, {%0,%1,%2,%3};"
        : "+f"(c[0]), "+f"(c[1]), "+f"(c[2]), "+f"(c[3])
        : "r"(a[0]), "r"(a[1]), "r"(a[2]), "r"(a[3]), "r"(b0), "r"(b1));
}

// ---------------- small kernels ----------------
__global__ void zero_stats_kernel() {
    int i = threadIdx.x;
    if (i < 3 * DDIM) { g_sum[i] = 0.f; g_sumsq[i] = 0.f; }
}

__global__ void finalize_stats_kernel(int layer, const float* __restrict__ g,
                                      const float* __restrict__ be) {
    int c = threadIdx.x;
    const float inv = 1.0f / (float)NROWS;
    float mu  = g_sum  [layer * DDIM + c] * inv;
    float var = g_sumsq[layer * DDIM + c] * inv - mu * mu;
    float s = rsqrtf(var + EPSV) * g[c];
    g_scale[layer * DDIM + c] = s;
    g_shift[layer * DDIM + c] = be[c] - mu * s;
}

__global__ void gather_split_kernel(const int* __restrict__ ids,
                                    const float* __restrict__ table) {
    int idx = blockIdx.x * blockDim.x + threadIdx.x;   // float4 index
    int row = idx >> 6;
    int q   = idx & 63;
    int src = ids[row];
    float4 v = reinterpret_cast<const float4*>(table + (size_t)src * DDIM)[q];
    uint2 o;
    o.x = pack2h(__float2half(v.x), __float2half(v.y));
    o.y = pack2h(__float2half(v.z), __float2half(v.w));
    reinterpret_cast<uint2*>(g_X)[idx] = o;
}

__global__ void prep_w_kernel(const float* __restrict__ W, const float* __restrict__ b,
                              int layer, int use_bn) {
    __shared__ float red[DDIM];
    int n = blockIdx.x, k = threadIdx.x;
    float w = W[k * DDIM + n];
    float s = 1.f, t = 0.f;
    if (use_bn) {
        s = g_scale[(layer - 1) * DDIM + k];
        t = g_shift[(layer - 1) * DDIM + k];
    }
    __half h, l;
    split2h(w * s, h, l);
    g_Bhi[layer][n * DDIM + k] = h;
    g_Blo[layer][n * DDIM + k] = l;
    red[k] = t * w;
    __syncthreads();
    for (int st = 128; st > 0; st >>= 1) {
        if (k < st) red[k] += red[k + st];
        __syncthreads();
    }
    if (k == 0) g_bias[layer][n] = b[n] + red[0];
}

// ---------------- main fused GEMM layer (HMMA fp16, A-single x B-split, 2 products) ----
// CTA: M=64 x N=128, 4 warps (2M x 2N), warp tile 32x64, 4 CTAs/SM.
// K chunks of 32, 2-stage cp.async pipeline, two light barriers per chunk.
template<int STATS, int FINAL>
__global__ __launch_bounds__(128, 4)
void gemm_kernel(const __half* __restrict__ A,
                 const __half* __restrict__ Bhi,
                 const __half* __restrict__ Blo,
                 const float* __restrict__ bias,
                 int layer,
                 float* __restrict__ outF,
                 __half* __restrict__ outH)
{
    extern __shared__ char dyn_smem[];
    const int tid  = threadIdx.x;
    const int lane = tid & 31;
    const int wid  = tid >> 5;
    const int m_warp = (wid >> 1) * 32;          // 2 M-groups (0, 32)
    const int n_warp = (wid & 1) * 64;           // 2 N-groups (0, 64)
    const int r0 = blockIdx.x * 64;
    const int c0 = blockIdx.y * 128;

    const uint32_t dyn0 = sm_u32(dyn_smem);
    const uint32_t su   = (dyn0 + 1023) & ~1023u;   // 1KB-aligned SMEM base

    float acc[2][8][4];
    #pragma unroll
    for (int i = 0; i < 2; i++)
        #pragma unroll
        for (int j = 0; j < 8; j++)
            #pragma unroll
            for (int q = 0; q < 4; q++) acc[i][j][q] = 0.f;

    // --- cp.async issue of one K-chunk (KC=32, 64B rows) into stage c%2 ---
    auto issue = [&](int c) {
        const uint32_t sb = su + (c & 1) * STAGE_BYTES;
        const int kt = c * KC;
        #pragma unroll
        for (int i = 0; i < 2; i++) {   // A: 64 rows x 4 x 16B = 256 chunks
            int idx = tid + i * 128;
            int row = idx >> 2, q = idx & 3;
            uint32_t sw = swz64((uint32_t)(row * 64 + q * 16));
            CP16(sb + sw, A + (size_t)(r0 + row) * DDIM + kt + q * 8);
        }
        #pragma unroll
        for (int i = 0; i < 4; i++) {   // Bhi/Blo: 128 rows x 4 x 16B = 512 each
            int idx = tid + i * 128;
            int row = idx >> 2, q = idx & 3;
            uint32_t sw = swz64((uint32_t)(row * 64 + q * 16));
            const size_t g = (size_t)(c0 + row) * DDIM + kt + q * 8;
            CP16(sb + 4096 + sw,  Bhi + g);
            CP16(sb + 12288 + sw, Blo + g);
        }
        CP_COMMIT();
    };

    // prologue: fill both stages
    issue(0); issue(1);

    // A-frag lane addressing (row-major A, 16x16 frag = 4 m8n8)
    const uint32_t a_row = (uint32_t)(lane & 15);
    const uint32_t a_kh  = (uint32_t)(lane >> 4);
    // B-frag lane addressing (paired j/j+1 in one x4)
    const uint32_t b_row = (uint32_t)(((lane >> 4) & 1) * 8 + (lane & 7));
    const uint32_t b_kh  = (uint32_t)((lane >> 3) & 1);

    #pragma unroll
    for (int c = 0; c < NCHUNK; c++) {
        if (c < NCHUNK - 1) CP_WAITN(1); else CP_WAITN(0);
        __syncthreads();

        const uint32_t sa = su + (c & 1) * STAGE_BYTES;
        #pragma unroll
        for (int ks = 0; ks < 2; ks++) {
            uint32_t a_f[2][4];
            #pragma unroll
            for (int i = 0; i < 2; i++) {
                uint32_t off = (m_warp + i * 16 + a_row) * 64 + ks * 32 + a_kh * 16;
                LDSM_X4(a_f[i], sa + swz64(off));
            }
            #pragma unroll
            for (int jp = 0; jp < 4; jp++) {
                uint32_t off = (n_warp + jp * 16 + b_row) * 64 + ks * 32 + b_kh * 16;
                uint32_t ad = sa + 4096 + swz64(off);
                uint32_t bh[4], bl[4];
                LDSM_X4(bh, ad);
                LDSM_X4(bl, ad + 8192);
                // product-major: same accumulator reused at distance 4
                mma16816(acc[0][2 * jp],     a_f[0], bh[0], bh[1]);
                mma16816(acc[1][2 * jp],     a_f[1], bh[0], bh[1]);
                mma16816(acc[0][2 * jp + 1], a_f[0], bh[2], bh[3]);
                mma16816(acc[1][2 * jp + 1], a_f[1], bh[2], bh[3]);
                mma16816(acc[0][2 * jp],     a_f[0], bl[0], bl[1]);
                mma16816(acc[1][2 * jp],     a_f[1], bl[0], bl[1]);
                mma16816(acc[0][2 * jp + 1], a_f[0], bl[2], bl[3]);
                mma16816(acc[1][2 * jp + 1], a_f[1], bl[2], bl[3]);
            }
        }

        __syncthreads();                    // all warps done with stage c&1
        if (c + 2 < NCHUNK) issue(c + 2);   // safe to overwrite it now
    }

    // ---- epilogue: bias + exact GELU + stores + column stats ----
    #pragma unroll
    for (int j = 0; j < 8; j++) {
        const int col0 = c0 + n_warp + j * 8 + (lane & 3) * 2;
        const float bi0 = bias[col0], bi1 = bias[col0 + 1];
        float su0 = 0.f, su1 = 0.f, sq0 = 0.f, sq1 = 0.f;
        #pragma unroll
        for (int i = 0; i < 2; i++) {
            const int rowA = r0 + m_warp + i * 16 + (lane >> 2);
            float v0 = gelu_exact(acc[i][j][0] + bi0);
            float v1 = gelu_exact(acc[i][j][1] + bi1);
            float v2 = gelu_exact(acc[i][j][2] + bi0);
            float v3 = gelu_exact(acc[i][j][3] + bi1);
            if (STATS) {
                su0 += v0 + v2; su1 += v1 + v3;
                sq0 += v0 * v0 + v2 * v2; sq1 += v1 * v1 + v3 * v3;
            }
            if (FINAL) {
                *reinterpret_cast<float2*>(outF + (size_t)rowA * DDIM + col0)
                    = make_float2(v0, v1);
                *reinterpret_cast<float2*>(outF + (size_t)(rowA + 8) * DDIM + col0)
                    = make_float2(v2, v3);
            } else {
                *reinterpret_cast<uint32_t*>(outH + (size_t)rowA * DDIM + col0)
                    = pack2h(__float2half(v0), __float2half(v1));
                *reinterpret_cast<uint32_t*>(outH + (size_t)(rowA + 8) * DDIM + col0)
                    = pack2h(__float2half(v2), __float2half(v3));
            }
        }
        if (STATS) {
            #pragma unroll
            for (int m = 4; m <= 16; m <<= 1) {
                su0 += __shfl_xor_sync(0xFFFFFFFFu, su0, m);
                su1 += __shfl_xor_sync(0xFFFFFFFFu, su1, m);
                sq0 += __shfl_xor_sync(0xFFFFFFFFu, sq0, m);
                sq1 += __shfl_xor_sync(0xFFFFFFFFu, sq1, m);
            }
            if ((lane >> 2) == 0) {
                atomicAdd(&g_sum  [layer * DDIM + col0],     su0);
                atomicAdd(&g_sum  [layer * DDIM + col0 + 1], su1);
                atomicAdd(&g_sumsq[layer * DDIM + col0],     sq0);
                atomicAdd(&g_sumsq[layer * DDIM + col0 + 1], sq1);
            }
        }
    }
}

// ---------------- launch ----------------
extern "C" void kernel_launch(void* const* d_in, const int* in_sizes, int n_in,
                              void* d_out, int out_size) {
    const int*   ids   = (const int*)  d_in[0];
    const float* table = (const float*)d_in[1];
    const float* W[4]  = {(const float*)d_in[2], (const float*)d_in[4],
                          (const float*)d_in[6], (const float*)d_in[8]};
    const float* b[4]  = {(const float*)d_in[3], (const float*)d_in[5],
                          (const float*)d_in[7], (const float*)d_in[9]};
    const float* g[3]  = {(const float*)d_in[10], (const float*)d_in[12], (const float*)d_in[14]};
    const float* be[3] = {(const float*)d_in[11], (const float*)d_in[13], (const float*)d_in[15]};
    float* out = (float*)d_out;

    cudaFuncSetAttribute(gemm_kernel<1, 0>, cudaFuncAttributeMaxDynamicSharedMemorySize, SMEM_DYN);
    cudaFuncSetAttribute(gemm_kernel<0, 1>, cudaFuncAttributeMaxDynamicSharedMemorySize, SMEM_DYN);

    __half *X, *Y, *Bh, *Bl;
    float *bs;
    cudaGetSymbolAddress((void**)&X,  g_X);
    cudaGetSymbolAddress((void**)&Y,  g_Y);
    cudaGetSymbolAddress((void**)&Bh, g_Bhi);
    cudaGetSymbolAddress((void**)&Bl, g_Blo);
    cudaGetSymbolAddress((void**)&bs, g_bias);

    const dim3 grid(NROWS / 64, DDIM / 128), blk(128);

    zero_stats_kernel<<<1, 768>>>();
    gather_split_kernel<<<NROWS * DDIM / 4 / 256, 256>>>(ids, table);
    prep_w_kernel<<<DDIM, DDIM>>>(W[0], b[0], 0, 0);

    gemm_kernel<1, 0><<<grid, blk, SMEM_DYN>>>(
        X, Bh + 0 * DDIM * DDIM, Bl + 0 * DDIM * DDIM, bs + 0 * DDIM,
        0, nullptr, Y);
    finalize_stats_kernel<<<1, DDIM>>>(0, g[0], be[0]);
    prep_w_kernel<<<DDIM, DDIM>>>(W[1], b[1], 1, 1);

    gemm_kernel<1, 0><<<grid, blk, SMEM_DYN>>>(
        Y, Bh + 1 * DDIM * DDIM, Bl + 1 * DDIM * DDIM, bs + 1 * DDIM,
        1, nullptr, X);
    finalize_stats_kernel<<<1, DDIM>>>(1, g[1], be[1]);
    prep_w_kernel<<<DDIM, DDIM>>>(W[2], b[2], 2, 1);

    gemm_kernel<1, 0><<<grid, blk, SMEM_DYN>>>(
        X, Bh + 2 * DDIM * DDIM, Bl + 2 * DDIM * DDIM, bs + 2 * DDIM,
        2, nullptr, Y);
    finalize_stats_kernel<<<1, DDIM>>>(2, g[2], be[2]);
    prep_w_kernel<<<DDIM, DDIM>>>(W[3], b[3], 3, 1);

    gemm_kernel<0, 1><<<grid, blk, SMEM_DYN>>>(
        Y, Bh + 3 * DDIM * DDIM, Bl + 3 * DDIM * DDIM, bs + 3 * DDIM,
        3, out, nullptr);
}

// round 10
// speedup vs baseline: 1.5289x; 1.0004x over previous
#include <cuda_runtime.h>
#include <cuda_fp16.h>
#include <math.h>
#include <stdint.h>

#define NROWS 32768
#define DDIM  256
#define EPSV  1e-5f
#define KC    32
#define NCHUNK 8
#define STAGES 2
// Stage: A 4K | Bhi 8K | Blo 8K = 20K
#define STAGE_BYTES 20480
#define SMEM_DYN (STAGES * STAGE_BYTES + 1024)

// ---------------- device scratch (no allocations allowed) ----------------
__device__ __half g_X[NROWS * DDIM];
__device__ __half g_Y[NROWS * DDIM];
__device__ __half g_Bhi[4][DDIM * DDIM];   // B[n][k] = s_k * W[k][n], fp16 hi
__device__ __half g_Blo[4][DDIM * DDIM];   // fp16 residual
__device__ float g_bias [4][DDIM];          // b'[n] = b[n] + sum_k t_k W[k][n]
__device__ float g_sum  [3 * DDIM];
__device__ float g_sumsq[3 * DDIM];
__device__ float g_scale[3 * DDIM];
__device__ float g_shift[3 * DDIM];

// ---------------- helpers ----------------
__device__ __forceinline__ uint32_t sm_u32(const void* p) {
    return (uint32_t)__cvta_generic_to_shared(p);
}
__device__ __forceinline__ float gelu_exact(float x) {
    return 0.5f * x * (1.0f + erff(x * 0.70710678118654752440f));
}
__device__ __forceinline__ void split2h(float v, __half& h, __half& l) {
    h = __float2half(v);
    l = __float2half(v - __half2float(h));
}
__device__ __forceinline__ uint32_t pack2h(__half a, __half b) {
    __half2 t = __halves2half2(a, b);
    return *reinterpret_cast<uint32_t*>(&t);
}
// SW64 swizzle for 64-byte rows (8-row x 64B atom)
__device__ __forceinline__ uint32_t swz64(uint32_t off) {
    return off ^ ((off >> 3) & 0x30);
}

#define CP16(sm, gp) \
    asm volatile("cp.async.cg.shared.global [%0], [%1], 16;" :: "r"(sm), "l"(gp) : "memory")
#define CP_COMMIT() asm volatile("cp.async.commit_group;" ::: "memory")
#define CP_WAITN(n) asm volatile("cp.async.wait_group %0;" :: "n"(n) : "memory")

#define LDSM_X4(r, addr) \
    asm volatile("ldmatrix.sync.aligned.m8n8.x4.shared.b16 {%0,%1,%2,%3}, [%4];" \
        : "=r"((r)[0]), "=r"((r)[1]), "=r"((r)[2]), "=r"((r)[3]) : "r"(addr))

__device__ __forceinline__ void mma16816(float* c, const uint32_t* a, uint32_t b0, uint32_t b1) {
    asm volatile(
        "mma.sync.aligned.m16n8k16.row.col.f32.f16.f16.f32 "
        "{%0,%1,%2,%3}, {%4,%5,%6,%7}, {%8,%9}, {%0,%1,%2,%3};"
        : "+f"(c[0]), "+f"(c[1]), "+f"(c[2]), "+f"(c[3])
        : "r"(a[0]), "r"(a[1]), "r"(a[2]), "r"(a[3]), "r"(b0), "r"(b1));
}

// ---------------- small kernels ----------------
__global__ void zero_stats_kernel() {
    int i = threadIdx.x;
    if (i < 3 * DDIM) { g_sum[i] = 0.f; g_sumsq[i] = 0.f; }
}

__global__ void finalize_stats_kernel(int layer, const float* __restrict__ g,
                                      const float* __restrict__ be) {
    int c = threadIdx.x;
    const float inv = 1.0f / (float)NROWS;
    float mu  = g_sum  [layer * DDIM + c] * inv;
    float var = g_sumsq[layer * DDIM + c] * inv - mu * mu;
    float s = rsqrtf(var + EPSV) * g[c];
    g_scale[layer * DDIM + c] = s;
    g_shift[layer * DDIM + c] = be[c] - mu * s;
}

__global__ void gather_split_kernel(const int* __restrict__ ids,
                                    const float* __restrict__ table) {
    int idx = blockIdx.x * blockDim.x + threadIdx.x;   // float4 index
    int row = idx >> 6;
    int q   = idx & 63;
    int src = ids[row];
    float4 v = reinterpret_cast<const float4*>(table + (size_t)src * DDIM)[q];
    uint2 o;
    o.x = pack2h(__float2half(v.x), __float2half(v.y));
    o.y = pack2h(__float2half(v.z), __float2half(v.w));
    reinterpret_cast<uint2*>(g_X)[idx] = o;
}

__global__ void prep_w_kernel(const float* __restrict__ W, const float* __restrict__ b,
                              int layer, int use_bn) {
    __shared__ float red[DDIM];
    int n = blockIdx.x, k = threadIdx.x;
    float w = W[k * DDIM + n];
    float s = 1.f, t = 0.f;
    if (use_bn) {
        s = g_scale[(layer - 1) * DDIM + k];
        t = g_shift[(layer - 1) * DDIM + k];
    }
    __half h, l;
    split2h(w * s, h, l);
    g_Bhi[layer][n * DDIM + k] = h;
    g_Blo[layer][n * DDIM + k] = l;
    red[k] = t * w;
    __syncthreads();
    for (int st = 128; st > 0; st >>= 1) {
        if (k < st) red[k] += red[k + st];
        __syncthreads();
    }
    if (k == 0) g_bias[layer][n] = b[n] + red[0];
}

// ---------------- main fused GEMM layer (HMMA fp16, A-single x B-split, 2 products) ----
// CTA: M=64 x N=128, 4 warps (2M x 2N), warp tile 32x64, 4 CTAs/SM.
// K chunks of 32, 2-stage cp.async pipeline, two light barriers per chunk.
template<int STATS, int FINAL>
__global__ __launch_bounds__(128, 4)
void gemm_kernel(const __half* __restrict__ A,
                 const __half* __restrict__ Bhi,
                 const __half* __restrict__ Blo,
                 const float* __restrict__ bias,
                 int layer,
                 float* __restrict__ outF,
                 __half* __restrict__ outH)
{
    extern __shared__ char dyn_smem[];
    const int tid  = threadIdx.x;
    const int lane = tid & 31;
    const int wid  = tid >> 5;
    const int m_warp = (wid >> 1) * 32;          // 2 M-groups (0, 32)
    const int n_warp = (wid & 1) * 64;           // 2 N-groups (0, 64)
    const int r0 = blockIdx.x * 64;
    const int c0 = blockIdx.y * 128;

    const uint32_t dyn0 = sm_u32(dyn_smem);
    const uint32_t su   = (dyn0 + 1023) & ~1023u;   // 1KB-aligned SMEM base

    float acc[2][8][4];
    #pragma unroll
    for (int i = 0; i < 2; i++)
        #pragma unroll
        for (int j = 0; j < 8; j++)
            #pragma unroll
            for (int q = 0; q < 4; q++) acc[i][j][q] = 0.f;

    // --- cp.async issue of one K-chunk (KC=32, 64B rows) into stage c%2 ---
    auto issue = [&](int c) {
        const uint32_t sb = su + (c & 1) * STAGE_BYTES;
        const int kt = c * KC;
        #pragma unroll
        for (int i = 0; i < 2; i++) {   // A: 64 rows x 4 x 16B = 256 chunks
            int idx = tid + i * 128;
            int row = idx >> 2, q = idx & 3;
            uint32_t sw = swz64((uint32_t)(row * 64 + q * 16));
            CP16(sb + sw, A + (size_t)(r0 + row) * DDIM + kt + q * 8);
        }
        #pragma unroll
        for (int i = 0; i < 4; i++) {   // Bhi/Blo: 128 rows x 4 x 16B = 512 each
            int idx = tid + i * 128;
            int row = idx >> 2, q = idx & 3;
            uint32_t sw = swz64((uint32_t)(row * 64 + q * 16));
            const size_t g = (size_t)(c0 + row) * DDIM + kt + q * 8;
            CP16(sb + 4096 + sw,  Bhi + g);
            CP16(sb + 12288 + sw, Blo + g);
        }
        CP_COMMIT();
    };

    // prologue: fill both stages
    issue(0); issue(1);

    // A-frag lane addressing (row-major A, 16x16 frag = 4 m8n8)
    const uint32_t a_row = (uint32_t)(lane & 15);
    const uint32_t a_kh  = (uint32_t)(lane >> 4);
    // B-frag lane addressing (paired j/j+1 in one x4)
    const uint32_t b_row = (uint32_t)(((lane >> 4) & 1) * 8 + (lane & 7));
    const uint32_t b_kh  = (uint32_t)((lane >> 3) & 1);

    #pragma unroll
    for (int c = 0; c < NCHUNK; c++) {
        if (c < NCHUNK - 1) CP_WAITN(1); else CP_WAITN(0);
        __syncthreads();

        const uint32_t sa = su + (c & 1) * STAGE_BYTES;
        #pragma unroll
        for (int ks = 0; ks < 2; ks++) {
            uint32_t a_f[2][4];
            #pragma unroll
            for (int i = 0; i < 2; i++) {
                uint32_t off = (m_warp + i * 16 + a_row) * 64 + ks * 32 + a_kh * 16;
                LDSM_X4(a_f[i], sa + swz64(off));
            }
            #pragma unroll
            for (int jp = 0; jp < 4; jp++) {
                uint32_t off = (n_warp + jp * 16 + b_row) * 64 + ks * 32 + b_kh * 16;
                uint32_t ad = sa + 4096 + swz64(off);
                uint32_t bh[4], bl[4];
                LDSM_X4(bh, ad);
                LDSM_X4(bl, ad + 8192);
                // product-major: same accumulator reused at distance 4
                mma16816(acc[0][2 * jp],     a_f[0], bh[0], bh[1]);
                mma16816(acc[1][2 * jp],     a_f[1], bh[0], bh[1]);
                mma16816(acc[0][2 * jp + 1], a_f[0], bh[2], bh[3]);
                mma16816(acc[1][2 * jp + 1], a_f[1], bh[2], bh[3]);
                mma16816(acc[0][2 * jp],     a_f[0], bl[0], bl[1]);
                mma16816(acc[1][2 * jp],     a_f[1], bl[0], bl[1]);
                mma16816(acc[0][2 * jp + 1], a_f[0], bl[2], bl[3]);
                mma16816(acc[1][2 * jp + 1], a_f[1], bl[2], bl[3]);
            }
        }

        __syncthreads();                    // all warps done with stage c&1
        if (c + 2 < NCHUNK) issue(c + 2);   // safe to overwrite it now
    }

    // ---- epilogue: bias + exact GELU + stores + column stats ----
    #pragma unroll
    for (int j = 0; j < 8; j++) {
        const int col0 = c0 + n_warp + j * 8 + (lane & 3) * 2;
        const float bi0 = bias[col0], bi1 = bias[col0 + 1];
        float su0 = 0.f, su1 = 0.f, sq0 = 0.f, sq1 = 0.f;
        #pragma unroll
        for (int i = 0; i < 2; i++) {
            const int rowA = r0 + m_warp + i * 16 + (lane >> 2);
            float v0 = gelu_exact(acc[i][j][0] + bi0);
            float v1 = gelu_exact(acc[i][j][1] + bi1);
            float v2 = gelu_exact(acc[i][j][2] + bi0);
            float v3 = gelu_exact(acc[i][j][3] + bi1);
            if (STATS) {
                su0 += v0 + v2; su1 += v1 + v3;
                sq0 += v0 * v0 + v2 * v2; sq1 += v1 * v1 + v3 * v3;
            }
            if (FINAL) {
                *reinterpret_cast<float2*>(outF + (size_t)rowA * DDIM + col0)
                    = make_float2(v0, v1);
                *reinterpret_cast<float2*>(outF + (size_t)(rowA + 8) * DDIM + col0)
                    = make_float2(v2, v3);
            } else {
                *reinterpret_cast<uint32_t*>(outH + (size_t)rowA * DDIM + col0)
                    = pack2h(__float2half(v0), __float2half(v1));
                *reinterpret_cast<uint32_t*>(outH + (size_t)(rowA + 8) * DDIM + col0)
                    = pack2h(__float2half(v2), __float2half(v3));
            }
        }
        if (STATS) {
            #pragma unroll
            for (int m = 4; m <= 16; m <<= 1) {
                su0 += __shfl_xor_sync(0xFFFFFFFFu, su0, m);
                su1 += __shfl_xor_sync(0xFFFFFFFFu, su1, m);
                sq0 += __shfl_xor_sync(0xFFFFFFFFu, sq0, m);
                sq1 += __shfl_xor_sync(0xFFFFFFFFu, sq1, m);
            }
            if ((lane >> 2) == 0) {
                atomicAdd(&g_sum  [layer * DDIM + col0],     su0);
                atomicAdd(&g_sum  [layer * DDIM + col0 + 1], su1);
                atomicAdd(&g_sumsq[layer * DDIM + col0],     sq0);
                atomicAdd(&g_sumsq[layer * DDIM + col0 + 1], sq1);
            }
        }
    }
}

// ---------------- launch ----------------
extern "C" void kernel_launch(void* const* d_in, const int* in_sizes, int n_in,
                              void* d_out, int out_size) {
    const int*   ids   = (const int*)  d_in[0];
    const float* table = (const float*)d_in[1];
    const float* W[4]  = {(const float*)d_in[2], (const float*)d_in[4],
                          (const float*)d_in[6], (const float*)d_in[8]};
    const float* b[4]  = {(const float*)d_in[3], (const float*)d_in[5],
                          (const float*)d_in[7], (const float*)d_in[9]};
    const float* g[3]  = {(const float*)d_in[10], (const float*)d_in[12], (const float*)d_in[14]};
    const float* be[3] = {(const float*)d_in[11], (const float*)d_in[13], (const float*)d_in[15]};
    float* out = (float*)d_out;

    cudaFuncSetAttribute(gemm_kernel<1, 0>, cudaFuncAttributeMaxDynamicSharedMemorySize, SMEM_DYN);
    cudaFuncSetAttribute(gemm_kernel<0, 1>, cudaFuncAttributeMaxDynamicSharedMemorySize, SMEM_DYN);

    __half *X, *Y, *Bh, *Bl;
    float *bs;
    cudaGetSymbolAddress((void**)&X,  g_X);
    cudaGetSymbolAddress((void**)&Y,  g_Y);
    cudaGetSymbolAddress((void**)&Bh, g_Bhi);
    cudaGetSymbolAddress((void**)&Bl, g_Blo);
    cudaGetSymbolAddress((void**)&bs, g_bias);

    const dim3 grid(NROWS / 64, DDIM / 128), blk(128);

    zero_stats_kernel<<<1, 768>>>();
    gather_split_kernel<<<NROWS * DDIM / 4 / 256, 256>>>(ids, table);
    prep_w_kernel<<<DDIM, DDIM>>>(W[0], b[0], 0, 0);

    gemm_kernel<1, 0><<<grid, blk, SMEM_DYN>>>(
        X, Bh + 0 * DDIM * DDIM, Bl + 0 * DDIM * DDIM, bs + 0 * DDIM,
        0, nullptr, Y);
    finalize_stats_kernel<<<1, DDIM>>>(0, g[0], be[0]);
    prep_w_kernel<<<DDIM, DDIM>>>(W[1], b[1], 1, 1);

    gemm_kernel<1, 0><<<grid, blk, SMEM_DYN>>>(
        Y, Bh + 1 * DDIM * DDIM, Bl + 1 * DDIM * DDIM, bs + 1 * DDIM,
        1, nullptr, X);
    finalize_stats_kernel<<<1, DDIM>>>(1, g[1], be[1]);
    prep_w_kernel<<<DDIM, DDIM>>>(W[2], b[2], 2, 1);

    gemm_kernel<1, 0><<<grid, blk, SMEM_DYN>>>(
        X, Bh + 2 * DDIM * DDIM, Bl + 2 * DDIM * DDIM, bs + 2 * DDIM,
        2, nullptr, Y);
    finalize_stats_kernel<<<1, DDIM>>>(2, g[2], be[2]);
    prep_w_kernel<<<DDIM, DDIM>>>(W[3], b[3], 3, 1);

    gemm_kernel<0, 1><<<grid, blk, SMEM_DYN>>>(
        Y, Bh + 3 * DDIM * DDIM, Bl + 3 * DDIM * DDIM, bs + 3 * DDIM,
        3, out, nullptr);
}

// round 11
// speedup vs baseline: 1.5484x; 1.0128x over previous
#include <cuda_runtime.h>
#include <cuda_fp16.h>
#include <math.h>
#include <stdint.h>

#define NROWS 32768
#define DDIM  256
#define EPSV  1e-5f
#define KC    32
#define NCHUNK 8
#define STAGES 4
// Stage: A 8K | Bhi 8K | Blo 8K = 24K
#define STAGE_BYTES 24576
#define SMEM_DYN (STAGES * STAGE_BYTES + 1024)

// ---------------- device scratch (no allocations allowed) ----------------
__device__ __half g_X[NROWS * DDIM];
__device__ __half g_Y[NROWS * DDIM];
__device__ __half g_Bhi[4][DDIM * DDIM];   // B[n][k] = s_k * W[k][n], fp16 hi
__device__ __half g_Blo[4][DDIM * DDIM];   // fp16 residual
__device__ float g_bias [4][DDIM];          // b'[n] = b[n] + sum_k t_k W[k][n]
__device__ float g_sum  [3 * DDIM];
__device__ float g_sumsq[3 * DDIM];
__device__ float g_scale[3 * DDIM];
__device__ float g_shift[3 * DDIM];

// ---------------- helpers ----------------
__device__ __forceinline__ uint32_t sm_u32(const void* p) {
    return (uint32_t)__cvta_generic_to_shared(p);
}
__device__ __forceinline__ float gelu_exact(float x) {
    return 0.5f * x * (1.0f + erff(x * 0.70710678118654752440f));
}
__device__ __forceinline__ void split2h(float v, __half& h, __half& l) {
    h = __float2half(v);
    l = __float2half(v - __half2float(h));
}
__device__ __forceinline__ uint32_t pack2h(__half a, __half b) {
    __half2 t = __halves2half2(a, b);
    return *reinterpret_cast<uint32_t*>(&t);
}
// SW64 swizzle for 64-byte rows (8-row x 64B atom)
__device__ __forceinline__ uint32_t swz64(uint32_t off) {
    return off ^ ((off >> 3) & 0x30);
}

#define CP16(sm, gp) \
    asm volatile("cp.async.cg.shared.global [%0], [%1], 16;" :: "r"(sm), "l"(gp) : "memory")
#define CP_COMMIT() asm volatile("cp.async.commit_group;" ::: "memory")
#define CP_WAITN(n) asm volatile("cp.async.wait_group %0;" :: "n"(n) : "memory")

#define LDSM_X4(r, addr) \
    asm volatile("ldmatrix.sync.aligned.m8n8.x4.shared.b16 {%0,%1,%2,%3}, [%4];" \
        : "=r"((r)[0]), "=r"((r)[1]), "=r"((r)[2]), "=r"((r)[3]) : "r"(addr))

__device__ __forceinline__ void mma16816(float* c, const uint32_t* a, uint32_t b0, uint32_t b1) {
    asm volatile(
        "mma.sync.aligned.m16n8k16.row.col.f32.f16.f16.f32 "
        "{%0,%1,%2,%3}, {%4,%5,%6,%7}, {%8,%9}, {%0,%1,%2,%3};"
        : "+f"(c[0]), "+f"(c[1]), "+f"(c[2]), "+f"(c[3])
        : "r"(a[0]), "r"(a[1]), "r"(a[2]), "r"(a[3]), "r"(b0), "r"(b1));
}

// ---------------- small kernels ----------------
__global__ void zero_stats_kernel() {
    int i = threadIdx.x;
    if (i < 3 * DDIM) { g_sum[i] = 0.f; g_sumsq[i] = 0.f; }
}

__global__ void finalize_stats_kernel(int layer, const float* __restrict__ g,
                                      const float* __restrict__ be) {
    int c = threadIdx.x;
    const float inv = 1.0f / (float)NROWS;
    float mu  = g_sum  [layer * DDIM + c] * inv;
    float var = g_sumsq[layer * DDIM + c] * inv - mu * mu;
    float s = rsqrtf(var + EPSV) * g[c];
    g_scale[layer * DDIM + c] = s;
    g_shift[layer * DDIM + c] = be[c] - mu * s;
}

__global__ void gather_split_kernel(const int* __restrict__ ids,
                                    const float* __restrict__ table) {
    int idx = blockIdx.x * blockDim.x + threadIdx.x;   // float4 index
    int row = idx >> 6;
    int q   = idx & 63;
    int src = ids[row];
    float4 v = reinterpret_cast<const float4*>(table + (size_t)src * DDIM)[q];
    uint2 o;
    o.x = pack2h(__float2half(v.x), __float2half(v.y));
    o.y = pack2h(__float2half(v.z), __float2half(v.w));
    reinterpret_cast<uint2*>(g_X)[idx] = o;
}

__global__ void prep_w_kernel(const float* __restrict__ W, const float* __restrict__ b,
                              int layer, int use_bn) {
    __shared__ float red[DDIM];
    int n = blockIdx.x, k = threadIdx.x;
    float w = W[k * DDIM + n];
    float s = 1.f, t = 0.f;
    if (use_bn) {
        s = g_scale[(layer - 1) * DDIM + k];
        t = g_shift[(layer - 1) * DDIM + k];
    }
    __half h, l;
    split2h(w * s, h, l);
    g_Bhi[layer][n * DDIM + k] = h;
    g_Blo[layer][n * DDIM + k] = l;
    red[k] = t * w;
    __syncthreads();
    for (int st = 128; st > 0; st >>= 1) {
        if (k < st) red[k] += red[k + st];
        __syncthreads();
    }
    if (k == 0) g_bias[layer][n] = b[n] + red[0];
}

// ---------------- main fused GEMM layer (HMMA fp16, A-single x B-split, 2 products) ----
// CTA: M=128 x N=128, 8 warps (4M x 2N), warp tile 32x64, 2 CTAs/SM.
// K chunks of 32, 4-stage cp.async pipeline, one barrier per chunk.
// Register double-buffered fragments: group g+1's LDSMs issue before group g's MMAs.
template<int STATS, int FINAL>
__global__ __launch_bounds__(256, 2)
void gemm_kernel(const __half* __restrict__ A,
                 const __half* __restrict__ Bhi,
                 const __half* __restrict__ Blo,
                 const float* __restrict__ bias,
                 int layer,
                 float* __restrict__ outF,
                 __half* __restrict__ outH)
{
    extern __shared__ char dyn_smem[];
    const int tid  = threadIdx.x;
    const int lane = tid & 31;
    const int wid  = tid >> 5;
    const int m_warp = (wid >> 1) * 32;          // 4 M-groups
    const int n_warp = (wid & 1) * 64;           // 2 N-groups
    const int r0 = blockIdx.x * 128;
    const int c0 = blockIdx.y * 128;

    const uint32_t dyn0 = sm_u32(dyn_smem);
    const uint32_t su   = (dyn0 + 1023) & ~1023u;   // 1KB-aligned SMEM base

    float acc[2][8][4];
    #pragma unroll
    for (int i = 0; i < 2; i++)
        #pragma unroll
        for (int j = 0; j < 8; j++)
            #pragma unroll
            for (int q = 0; q < 4; q++) acc[i][j][q] = 0.f;

    // --- cp.async issue of one K-chunk (KC=32, 64B rows) into stage c%4 ---
    auto issue = [&](int c) {
        const uint32_t sb = su + (c & 3) * STAGE_BYTES;
        const int kt = c * KC;
        #pragma unroll
        for (int i = 0; i < 2; i++) {   // A: 128 rows x 4 x 16B = 512 chunks
            int idx = tid + i * 256;
            int row = idx >> 2, q = idx & 3;
            uint32_t sw = swz64((uint32_t)(row * 64 + q * 16));
            CP16(sb + sw, A + (size_t)(r0 + row) * DDIM + kt + q * 8);
        }
        #pragma unroll
        for (int i = 0; i < 2; i++) {   // Bhi/Blo: 128 rows x 4 x 16B = 512 each
            int idx = tid + i * 256;
            int row = idx >> 2, q = idx & 3;
            uint32_t sw = swz64((uint32_t)(row * 64 + q * 16));
            const size_t g = (size_t)(c0 + row) * DDIM + kt + q * 8;
            CP16(sb + 8192 + sw,  Bhi + g);
            CP16(sb + 16384 + sw, Blo + g);
        }
        CP_COMMIT();
    };

    // prologue: fill 3 stages
    issue(0); issue(1); issue(2);

    // A-frag lane addressing (row-major A, 16x16 frag = 4 m8n8)
    const uint32_t a_row = (uint32_t)(lane & 15);
    const uint32_t a_kh  = (uint32_t)(lane >> 4);
    // B-frag lane addressing (paired j/j+1 in one x4)
    const uint32_t b_row = (uint32_t)(((lane >> 4) & 1) * 8 + (lane & 7));
    const uint32_t b_kh  = (uint32_t)((lane >> 3) & 1);

    #pragma unroll
    for (int c = 0; c < NCHUNK; c++) {
        if      (c <  NCHUNK - 2) CP_WAITN(2);
        else if (c == NCHUNK - 2) CP_WAITN(1);
        else                      CP_WAITN(0);
        __syncthreads();
        if (c + 3 < NCHUNK) issue(c + 3);

        const uint32_t sa = su + (c & 3) * STAGE_BYTES;

        // fragment register double-buffers
        uint32_t a_f[2][2][4];        // [ks][i][4]
        uint32_t bh[2][4], bl[2][4];  // [buf][4]

        // preload group 0 (ks=0, jp=0) + A(ks=0)
        #pragma unroll
        for (int i = 0; i < 2; i++) {
            uint32_t off = (m_warp + i * 16 + a_row) * 64 + a_kh * 16;
            LDSM_X4(a_f[0][i], sa + swz64(off));
        }
        {
            uint32_t off = (n_warp + b_row) * 64 + b_kh * 16;
            uint32_t ad = sa + 8192 + swz64(off);
            LDSM_X4(bh[0], ad);
            LDSM_X4(bl[0], ad + 8192);
        }

        #pragma unroll
        for (int g = 0; g < 8; g++) {      // g = ks*4 + jp
            const int ks = g >> 2, jp = g & 3;
            const int cb = g & 1, nb = cb ^ 1;
            // prefetch group g+1 fragments BEFORE this group's MMAs
            if (g < 7) {
                const int gn = g + 1, ksn = gn >> 2, jpn = gn & 3;
                uint32_t offb = (n_warp + jpn * 16 + b_row) * 64 + ksn * 32 + b_kh * 16;
                uint32_t adb = sa + 8192 + swz64(offb);
                LDSM_X4(bh[nb], adb);
                LDSM_X4(bl[nb], adb + 8192);
                if (jpn == 0) {            // crossing into ks=1: prefetch A frags
                    #pragma unroll
                    for (int i = 0; i < 2; i++) {
                        uint32_t offa = (m_warp + i * 16 + a_row) * 64 + ksn * 32 + a_kh * 16;
                        LDSM_X4(a_f[ksn][i], sa + swz64(offa));
                    }
                }
            }
            // 8 MMAs, product-major: same accumulator reused at distance 4
            mma16816(acc[0][2 * jp],     a_f[ks][0], bh[cb][0], bh[cb][1]);
            mma16816(acc[1][2 * jp],     a_f[ks][1], bh[cb][0], bh[cb][1]);
            mma16816(acc[0][2 * jp + 1], a_f[ks][0], bh[cb][2], bh[cb][3]);
            mma16816(acc[1][2 * jp + 1], a_f[ks][1], bh[cb][2], bh[cb][3]);
            mma16816(acc[0][2 * jp],     a_f[ks][0], bl[cb][0], bl[cb][1]);
            mma16816(acc[1][2 * jp],     a_f[ks][1], bl[cb][0], bl[cb][1]);
            mma16816(acc[0][2 * jp + 1], a_f[ks][0], bl[cb][2], bl[cb][3]);
            mma16816(acc[1][2 * jp + 1], a_f[ks][1], bl[cb][2], bl[cb][3]);
        }
    }

    // ---- epilogue: bias + exact GELU + stores + column stats ----
    #pragma unroll
    for (int j = 0; j < 8; j++) {
        const int col0 = c0 + n_warp + j * 8 + (lane & 3) * 2;
        const float bi0 = bias[col0], bi1 = bias[col0 + 1];
        float su0 = 0.f, su1 = 0.f, sq0 = 0.f, sq1 = 0.f;
        #pragma unroll
        for (int i = 0; i < 2; i++) {
            const int rowA = r0 + m_warp + i * 16 + (lane >> 2);
            float v0 = gelu_exact(acc[i][j][0] + bi0);
            float v1 = gelu_exact(acc[i][j][1] + bi1);
            float v2 = gelu_exact(acc[i][j][2] + bi0);
            float v3 = gelu_exact(acc[i][j][3] + bi1);
            if (STATS) {
                su0 += v0 + v2; su1 += v1 + v3;
                sq0 += v0 * v0 + v2 * v2; sq1 += v1 * v1 + v3 * v3;
            }
            if (FINAL) {
                *reinterpret_cast<float2*>(outF + (size_t)rowA * DDIM + col0)
                    = make_float2(v0, v1);
                *reinterpret_cast<float2*>(outF + (size_t)(rowA + 8) * DDIM + col0)
                    = make_float2(v2, v3);
            } else {
                *reinterpret_cast<uint32_t*>(outH + (size_t)rowA * DDIM + col0)
                    = pack2h(__float2half(v0), __float2half(v1));
                *reinterpret_cast<uint32_t*>(outH + (size_t)(rowA + 8) * DDIM + col0)
                    = pack2h(__float2half(v2), __float2half(v3));
            }
        }
        if (STATS) {
            #pragma unroll
            for (int m = 4; m <= 16; m <<= 1) {
                su0 += __shfl_xor_sync(0xFFFFFFFFu, su0, m);
                su1 += __shfl_xor_sync(0xFFFFFFFFu, su1, m);
                sq0 += __shfl_xor_sync(0xFFFFFFFFu, sq0, m);
                sq1 += __shfl_xor_sync(0xFFFFFFFFu, sq1, m);
            }
            if ((lane >> 2) == 0) {
                atomicAdd(&g_sum  [layer * DDIM + col0],     su0);
                atomicAdd(&g_sum  [layer * DDIM + col0 + 1], su1);
                atomicAdd(&g_sumsq[layer * DDIM + col0],     sq0);
                atomicAdd(&g_sumsq[layer * DDIM + col0 + 1], sq1);
            }
        }
    }
}

// ---------------- launch ----------------
extern "C" void kernel_launch(void* const* d_in, const int* in_sizes, int n_in,
                              void* d_out, int out_size) {
    const int*   ids   = (const int*)  d_in[0];
    const float* table = (const float*)d_in[1];
    const float* W[4]  = {(const float*)d_in[2], (const float*)d_in[4],
                          (const float*)d_in[6], (const float*)d_in[8]};
    const float* b[4]  = {(const float*)d_in[3], (const float*)d_in[5],
                          (const float*)d_in[7], (const float*)d_in[9]};
    const float* g[3]  = {(const float*)d_in[10], (const float*)d_in[12], (const float*)d_in[14]};
    const float* be[3] = {(const float*)d_in[11], (const float*)d_in[13], (const float*)d_in[15]};
    float* out = (float*)d_out;

    cudaFuncSetAttribute(gemm_kernel<1, 0>, cudaFuncAttributeMaxDynamicSharedMemorySize, SMEM_DYN);
    cudaFuncSetAttribute(gemm_kernel<0, 1>, cudaFuncAttributeMaxDynamicSharedMemorySize, SMEM_DYN);

    __half *X, *Y, *Bh, *Bl;
    float *bs;
    cudaGetSymbolAddress((void**)&X,  g_X);
    cudaGetSymbolAddress((void**)&Y,  g_Y);
    cudaGetSymbolAddress((void**)&Bh, g_Bhi);
    cudaGetSymbolAddress((void**)&Bl, g_Blo);
    cudaGetSymbolAddress((void**)&bs, g_bias);

    const dim3 grid(NROWS / 128, DDIM / 128), blk(256);

    zero_stats_kernel<<<1, 768>>>();
    gather_split_kernel<<<NROWS * DDIM / 4 / 256, 256>>>(ids, table);
    prep_w_kernel<<<DDIM, DDIM>>>(W[0], b[0], 0, 0);

    gemm_kernel<1, 0><<<grid, blk, SMEM_DYN>>>(
        X, Bh + 0 * DDIM * DDIM, Bl + 0 * DDIM * DDIM, bs + 0 * DDIM,
        0, nullptr, Y);
    finalize_stats_kernel<<<1, DDIM>>>(0, g[0], be[0]);
    prep_w_kernel<<<DDIM, DDIM>>>(W[1], b[1], 1, 1);

    gemm_kernel<1, 0><<<grid, blk, SMEM_DYN>>>(
        Y, Bh + 1 * DDIM * DDIM, Bl + 1 * DDIM * DDIM, bs + 1 * DDIM,
        1, nullptr, X);
    finalize_stats_kernel<<<1, DDIM>>>(1, g[1], be[1]);
    prep_w_kernel<<<DDIM, DDIM>>>(W[2], b[2], 2, 1);

    gemm_kernel<1, 0><<<grid, blk, SMEM_DYN>>>(
        X, Bh + 2 * DDIM * DDIM, Bl + 2 * DDIM * DDIM, bs + 2 * DDIM,
        2, nullptr, Y);
    finalize_stats_kernel<<<1, DDIM>>>(2, g[2], be[2]);
    prep_w_kernel<<<DDIM, DDIM>>>(W[3], b[3], 3, 1);

    gemm_kernel<0, 1><<<grid, blk, SMEM_DYN>>>(
        Y, Bh + 3 * DDIM * DDIM, Bl + 3 * DDIM * DDIM, bs + 3 * DDIM,
        3, out, nullptr);
}

// round 13
// speedup vs baseline: 1.7351x; 1.1206x over previous
#include <cuda_runtime.h>
#include <cuda_fp16.h>
#include <math.h>
#include <stdint.h>

#define NROWS 32768
#define DDIM  256
#define EPSV  1e-5f
#define KC    32
#define NCHUNK 8
#define STAGES 4
// Stage: A 8K | B 8K = 16K
#define STAGE_BYTES 16384
#define SMEM_DYN (STAGES * STAGE_BYTES + 1024)

// ---------------- device scratch (no allocations allowed) ----------------
__device__ __half g_X[NROWS * DDIM];
__device__ __half g_Y[NROWS * DDIM];
__device__ __half g_B[4][DDIM * DDIM];     // B[n][k] = s_k * W[k][n], fp16
__device__ float g_bias [4][DDIM];          // b'[n] = b[n] + sum_k t_k W[k][n]
__device__ float g_sum  [3 * DDIM];
__device__ float g_sumsq[3 * DDIM];
__device__ float g_scale[3 * DDIM];
__device__ float g_shift[3 * DDIM];

// ---------------- helpers ----------------
__device__ __forceinline__ uint32_t sm_u32(const void* p) {
    return (uint32_t)__cvta_generic_to_shared(p);
}
__device__ __forceinline__ float gelu_exact(float x) {
    return 0.5f * x * (1.0f + erff(x * 0.70710678118654752440f));
}
__device__ __forceinline__ uint32_t pack2h(__half a, __half b) {
    __half2 t = __halves2half2(a, b);
    return *reinterpret_cast<uint32_t*>(&t);
}
// SW64 swizzle for 64-byte rows (8-row x 64B atom)
__device__ __forceinline__ uint32_t swz64(uint32_t off) {
    return off ^ ((off >> 3) & 0x30);
}

#define CP16(sm, gp) \
    asm volatile("cp.async.cg.shared.global [%0], [%1], 16;" :: "r"(sm), "l"(gp) : "memory")
#define CP_COMMIT() asm volatile("cp.async.commit_group;" ::: "memory")
#define CP_WAITN(n) asm volatile("cp.async.wait_group %0;" :: "n"(n) : "memory")

#define LDSM_X4(r, addr) \
    asm volatile("ldmatrix.sync.aligned.m8n8.x4.shared.b16 {%0,%1,%2,%3}, [%4];" \
        : "=r"((r)[0]), "=r"((r)[1]), "=r"((r)[2]), "=r"((r)[3]) : "r"(addr))

__device__ __forceinline__ void mma16816(float* c, const uint32_t* a, uint32_t b0, uint32_t b1) {
    asm volatile(
        "mma.sync.aligned.m16n8k16.row.col.f32.f16.f16.f32 "
        "{%0,%1,%2,%3}, {%4,%5,%6,%7}, {%8,%9}, {%0,%1,%2,%3};"
        : "+f"(c[0]), "+f"(c[1]), "+f"(c[2]), "+f"(c[3])
        : "r"(a[0]), "r"(a[1]), "r"(a[2]), "r"(a[3]), "r"(b0), "r"(b1));
}

// ---------------- small kernels ----------------
__global__ void zero_stats_kernel() {
    int i = threadIdx.x;
    if (i < 3 * DDIM) { g_sum[i] = 0.f; g_sumsq[i] = 0.f; }
}

__global__ void finalize_stats_kernel(int layer, const float* __restrict__ g,
                                      const float* __restrict__ be) {
    int c = threadIdx.x;
    const float inv = 1.0f / (float)NROWS;
    float mu  = g_sum  [layer * DDIM + c] * inv;
    float var = g_sumsq[layer * DDIM + c] * inv - mu * mu;
    float s = rsqrtf(var + EPSV) * g[c];
    g_scale[layer * DDIM + c] = s;
    g_shift[layer * DDIM + c] = be[c] - mu * s;
}

__global__ void gather_split_kernel(const int* __restrict__ ids,
                                    const float* __restrict__ table) {
    int idx = blockIdx.x * blockDim.x + threadIdx.x;   // float4 index
    int row = idx >> 6;
    int q   = idx & 63;
    int src = ids[row];
    float4 v = reinterpret_cast<const float4*>(table + (size_t)src * DDIM)[q];
    uint2 o;
    o.x = pack2h(__float2half(v.x), __float2half(v.y));
    o.y = pack2h(__float2half(v.z), __float2half(v.w));
    reinterpret_cast<uint2*>(g_X)[idx] = o;
}

__global__ void prep_w_kernel(const float* __restrict__ W, const float* __restrict__ b,
                              int layer, int use_bn) {
    __shared__ float red[DDIM];
    int n = blockIdx.x, k = threadIdx.x;
    float w = W[k * DDIM + n];
    float s = 1.f, t = 0.f;
    if (use_bn) {
        s = g_scale[(layer - 1) * DDIM + k];
        t = g_shift[(layer - 1) * DDIM + k];
    }
    g_B[layer][n * DDIM + k] = __float2half(w * s);
    red[k] = t * w;
    __syncthreads();
    for (int st = 128; st > 0; st >>= 1) {
        if (k < st) red[k] += red[k + st];
        __syncthreads();
    }
    if (k == 0) g_bias[layer][n] = b[n] + red[0];
}

// ---------------- main fused GEMM layer (HMMA fp16, single product) ----------------
// CTA: M=128 x N=128, 8 warps (4M x 2N), warp tile 32x64, 2 CTAs/SM.
// K chunks of 32, 4-stage cp.async pipeline, one barrier per chunk.
// Register double-buffered fragments: group g+1's LDSMs issue before group g's MMAs.
template<int STATS, int FINAL>
__global__ __launch_bounds__(256, 2)
void gemm_kernel(const __half* __restrict__ A,
                 const __half* __restrict__ B,
                 const float* __restrict__ bias,
                 int layer,
                 float* __restrict__ outF,
                 __half* __restrict__ outH)
{
    extern __shared__ char dyn_smem[];
    const int tid  = threadIdx.x;
    const int lane = tid & 31;
    const int wid  = tid >> 5;
    const int m_warp = (wid >> 1) * 32;          // 4 M-groups
    const int n_warp = (wid & 1) * 64;           // 2 N-groups
    const int r0 = blockIdx.x * 128;
    const int c0 = blockIdx.y * 128;

    const uint32_t dyn0 = sm_u32(dyn_smem);
    const uint32_t su   = (dyn0 + 1023) & ~1023u;   // 1KB-aligned SMEM base

    float acc[2][8][4];
    #pragma unroll
    for (int i = 0; i < 2; i++)
        #pragma unroll
        for (int j = 0; j < 8; j++)
            #pragma unroll
            for (int q = 0; q < 4; q++) acc[i][j][q] = 0.f;

    // --- cp.async issue of one K-chunk (KC=32, 64B rows) into stage c%4 ---
    auto issue = [&](int c) {
        const uint32_t sb = su + (c & 3) * STAGE_BYTES;
        const int kt = c * KC;
        #pragma unroll
        for (int i = 0; i < 2; i++) {   // A: 128 rows x 4 x 16B = 512 chunks
            int idx = tid + i * 256;
            int row = idx >> 2, q = idx & 3;
            uint32_t sw = swz64((uint32_t)(row * 64 + q * 16));
            CP16(sb + sw, A + (size_t)(r0 + row) * DDIM + kt + q * 8);
        }
        #pragma unroll
        for (int i = 0; i < 2; i++) {   // B: 128 rows x 4 x 16B = 512 chunks
            int idx = tid + i * 256;
            int row = idx >> 2, q = idx & 3;
            uint32_t sw = swz64((uint32_t)(row * 64 + q * 16));
            CP16(sb + 8192 + sw, B + (size_t)(c0 + row) * DDIM + kt + q * 8);
        }
        CP_COMMIT();
    };

    // prologue: fill 3 stages
    issue(0); issue(1); issue(2);

    // A-frag lane addressing (row-major A, 16x16 frag = 4 m8n8)
    const uint32_t a_row = (uint32_t)(lane & 15);
    const uint32_t a_kh  = (uint32_t)(lane >> 4);
    // B-frag lane addressing (paired j/j+1 in one x4)
    const uint32_t b_row = (uint32_t)(((lane >> 4) & 1) * 8 + (lane & 7));
    const uint32_t b_kh  = (uint32_t)((lane >> 3) & 1);

    #pragma unroll
    for (int c = 0; c < NCHUNK; c++) {
        if      (c <  NCHUNK - 2) CP_WAITN(2);
        else if (c == NCHUNK - 2) CP_WAITN(1);
        else                      CP_WAITN(0);
        __syncthreads();
        if (c + 3 < NCHUNK) issue(c + 3);

        const uint32_t sa = su + (c & 3) * STAGE_BYTES;

        // fragment register double-buffers
        uint32_t a_f[2][2][4];        // [ks][i][4]
        uint32_t bh[2][4];            // [buf][4]

        // preload group 0 (ks=0, jp=0) + A(ks=0)
        #pragma unroll
        for (int i = 0; i < 2; i++) {
            uint32_t off = (m_warp + i * 16 + a_row) * 64 + a_kh * 16;
            LDSM_X4(a_f[0][i], sa + swz64(off));
        }
        {
            uint32_t off = (n_warp + b_row) * 64 + b_kh * 16;
            LDSM_X4(bh[0], sa + 8192 + swz64(off));
        }

        #pragma unroll
        for (int g = 0; g < 8; g++) {      // g = ks*4 + jp
            const int ks = g >> 2, jp = g & 3;
            const int cb = g & 1, nb = cb ^ 1;
            // prefetch group g+1 fragments BEFORE this group's MMAs
            if (g < 7) {
                const int gn = g + 1, ksn = gn >> 2, jpn = gn & 3;
                uint32_t offb = (n_warp + jpn * 16 + b_row) * 64 + ksn * 32 + b_kh * 16;
                LDSM_X4(bh[nb], sa + 8192 + swz64(offb));
                if (jpn == 0) {            // crossing into ks=1: prefetch A frags
                    #pragma unroll
                    for (int i = 0; i < 2; i++) {
                        uint32_t offa = (m_warp + i * 16 + a_row) * 64 + ksn * 32 + a_kh * 16;
                        LDSM_X4(a_f[ksn][i], sa + swz64(offa));
                    }
                }
            }
            // 4 MMAs, each accumulator touched once per group
            mma16816(acc[0][2 * jp],     a_f[ks][0], bh[cb][0], bh[cb][1]);
            mma16816(acc[1][2 * jp],     a_f[ks][1], bh[cb][0], bh[cb][1]);
            mma16816(acc[0][2 * jp + 1], a_f[ks][0], bh[cb][2], bh[cb][3]);
            mma16816(acc[1][2 * jp + 1], a_f[ks][1], bh[cb][2], bh[cb][3]);
        }
    }

    // ---- epilogue: bias + exact GELU + stores + column stats ----
    #pragma unroll
    for (int j = 0; j < 8; j++) {
        const int col0 = c0 + n_warp + j * 8 + (lane & 3) * 2;
        const float bi0 = bias[col0], bi1 = bias[col0 + 1];
        float su0 = 0.f, su1 = 0.f, sq0 = 0.f, sq1 = 0.f;
        #pragma unroll
        for (int i = 0; i < 2; i++) {
            const int rowA = r0 + m_warp + i * 16 + (lane >> 2);
            float v0 = gelu_exact(acc[i][j][0] + bi0);
            float v1 = gelu_exact(acc[i][j][1] + bi1);
            float v2 = gelu_exact(acc[i][j][2] + bi0);
            float v3 = gelu_exact(acc[i][j][3] + bi1);
            if (STATS) {
                su0 += v0 + v2; su1 += v1 + v3;
                sq0 += v0 * v0 + v2 * v2; sq1 += v1 * v1 + v3 * v3;
            }
            if (FINAL) {
                *reinterpret_cast<float2*>(outF + (size_t)rowA * DDIM + col0)
                    = make_float2(v0, v1);
                *reinterpret_cast<float2*>(outF + (size_t)(rowA + 8) * DDIM + col0)
                    = make_float2(v2, v3);
            } else {
                *reinterpret_cast<uint32_t*>(outH + (size_t)rowA * DDIM + col0)
                    = pack2h(__float2half(v0), __float2half(v1));
                *reinterpret_cast<uint32_t*>(outH + (size_t)(rowA + 8) * DDIM + col0)
                    = pack2h(__float2half(v2), __float2half(v3));
            }
        }
        if (STATS) {
            #pragma unroll
            for (int m = 4; m <= 16; m <<= 1) {
                su0 += __shfl_xor_sync(0xFFFFFFFFu, su0, m);
                su1 += __shfl_xor_sync(0xFFFFFFFFu, su1, m);
                sq0 += __shfl_xor_sync(0xFFFFFFFFu, sq0, m);
                sq1 += __shfl_xor_sync(0xFFFFFFFFu, sq1, m);
            }
            if ((lane >> 2) == 0) {
                atomicAdd(&g_sum  [layer * DDIM + col0],     su0);
                atomicAdd(&g_sum  [layer * DDIM + col0 + 1], su1);
                atomicAdd(&g_sumsq[layer * DDIM + col0],     sq0);
                atomicAdd(&g_sumsq[layer * DDIM + col0 + 1], sq1);
            }
        }
    }
}

// ---------------- launch ----------------
extern "C" void kernel_launch(void* const* d_in, const int* in_sizes, int n_in,
                              void* d_out, int out_size) {
    const int*   ids   = (const int*)  d_in[0];
    const float* table = (const float*)d_in[1];
    const float* W[4]  = {(const float*)d_in[2], (const float*)d_in[4],
                          (const float*)d_in[6], (const float*)d_in[8]};
    const float* b[4]  = {(const float*)d_in[3], (const float*)d_in[5],
                          (const float*)d_in[7], (const float*)d_in[9]};
    const float* g[3]  = {(const float*)d_in[10], (const float*)d_in[12], (const float*)d_in[14]};
    const float* be[3] = {(const float*)d_in[11], (const float*)d_in[13], (const float*)d_in[15]};
    float* out = (float*)d_out;

    cudaFuncSetAttribute(gemm_kernel<1, 0>, cudaFuncAttributeMaxDynamicSharedMemorySize, SMEM_DYN);
    cudaFuncSetAttribute(gemm_kernel<0, 1>, cudaFuncAttributeMaxDynamicSharedMemorySize, SMEM_DYN);

    __half *X, *Y, *Bm;
    float *bs;
    cudaGetSymbolAddress((void**)&X,  g_X);
    cudaGetSymbolAddress((void**)&Y,  g_Y);
    cudaGetSymbolAddress((void**)&Bm, g_B);
    cudaGetSymbolAddress((void**)&bs, g_bias);

    const dim3 grid(NROWS / 128, DDIM / 128), blk(256);

    zero_stats_kernel<<<1, 768>>>();
    gather_split_kernel<<<NROWS * DDIM / 4 / 256, 256>>>(ids, table);
    prep_w_kernel<<<DDIM, DDIM>>>(W[0], b[0], 0, 0);

    gemm_kernel<1, 0><<<grid, blk, SMEM_DYN>>>(
        X, Bm + 0 * DDIM * DDIM, bs + 0 * DDIM, 0, nullptr, Y);
    finalize_stats_kernel<<<1, DDIM>>>(0, g[0], be[0]);
    prep_w_kernel<<<DDIM, DDIM>>>(W[1], b[1], 1, 1);

    gemm_kernel<1, 0><<<grid, blk, SMEM_DYN>>>(
        Y, Bm + 1 * DDIM * DDIM, bs + 1 * DDIM, 1, nullptr, X);
    finalize_stats_kernel<<<1, DDIM>>>(1, g[1], be[1]);
    prep_w_kernel<<<DDIM, DDIM>>>(W[2], b[2], 2, 1);

    gemm_kernel<1, 0><<<grid, blk, SMEM_DYN>>>(
        X, Bm + 2 * DDIM * DDIM, bs + 2 * DDIM, 2, nullptr, Y);
    finalize_stats_kernel<<<1, DDIM>>>(2, g[2], be[2]);
    prep_w_kernel<<<DDIM, DDIM>>>(W[3], b[3], 3, 1);

    gemm_kernel<0, 1><<<grid, blk, SMEM_DYN>>>(
        Y, Bm + 3 * DDIM * DDIM, bs + 3 * DDIM, 3, out, nullptr);
}